// round 9
// baseline (speedup 1.0000x reference)
#include <cuda_runtime.h>
#include <cuda_bf16.h>
#include <cstdint>

// ---------------- problem constants ----------------
#define NL    6
#define HD    1024
#define AD    1024
#define FI    4096
#define NBB   4
#define TSEQ  2048
#define NTOK  (NBB * TSEQ)     // 8192 tokens

// ---------------- GEMM tile constants ----------------
#define BM 128
#define BN 256
#define BK 64                  // bf16 elems per K tile (128B rows = SW128 atom)
#define STAGES 3
#define STAGE_A 16384
#define STAGE_B 32768
#define STAGE_BYTES (STAGE_A + STAGE_B)      // 49152
#define SMEM_SZ (STAGES * STAGE_BYTES)       // 147456

#define SWZ(o) ((o) ^ ((((uint32_t)(o)) >> 3) & 0x70))

// ---------------- persistent scratch ----------------
__device__ __align__(16) float g_h[NTOK * HD];
__device__ __align__(16) float g_k[NTOK * AD];
__device__ __align__(16) float g_v[NTOK * AD];
__device__ __align__(16) float g_r[NTOK * AD];
__device__ __align__(16) __nv_bfloat16 g_xkh[NTOK * HD], g_xkl[NTOK * HD];
__device__ __align__(16) __nv_bfloat16 g_xvh[NTOK * HD], g_xvl[NTOK * HD];
__device__ __align__(16) __nv_bfloat16 g_xrh[NTOK * HD], g_xrl[NTOK * HD];
__device__ __align__(16) __nv_bfloat16 g_yh[NTOK * AD], g_yl[NTOK * AD];
__device__ __align__(16) __nv_bfloat16 g_fkh[NTOK * FI], g_fkl[NTOK * FI];
// weight hi/lo
__device__ __align__(16) __nv_bfloat16 g_wkh[NL * AD * HD], g_wkl[NL * AD * HD];
__device__ __align__(16) __nv_bfloat16 g_wvh[NL * AD * HD], g_wvl[NL * AD * HD];
__device__ __align__(16) __nv_bfloat16 g_wrh[NL * AD * HD], g_wrl[NL * AD * HD];
__device__ __align__(16) __nv_bfloat16 g_woh[NL * HD * AD], g_wol[NL * HD * AD];
__device__ __align__(16) __nv_bfloat16 g_fwkh[NL * FI * HD], g_fwkl[NL * FI * HD];
__device__ __align__(16) __nv_bfloat16 g_fwrh[NL * HD * HD], g_fwrl[NL * HD * HD];
__device__ __align__(16) __nv_bfloat16 g_fwvh[NL * HD * FI], g_fwvl[NL * HD * FI];

// ---------------- PTX helpers (portable sm_80+ features only) ----------------
__device__ __forceinline__ uint32_t smem_u32(const void* p) {
    uint32_t a;
    asm("{ .reg .u64 t; cvta.to.shared.u64 t, %1; cvt.u32.u64 %0, t; }"
        : "=r"(a) : "l"(p));
    return a;
}

#define CPASYNC16(saddr, gptr)                                                \
    asm volatile("cp.async.cg.shared.global [%0], [%1], 16;"                  \
                 :: "r"(saddr), "l"(gptr))
#define CPCOMMIT() asm volatile("cp.async.commit_group;" ::: "memory")
#define CPWAIT1()  asm volatile("cp.async.wait_group 1;" ::: "memory")

#define LDSM4(r0, r1, r2, r3, addr)                                           \
    asm volatile("ldmatrix.sync.aligned.m8n8.x4.shared.b16 {%0,%1,%2,%3}, [%4];" \
                 : "=r"(r0), "=r"(r1), "=r"(r2), "=r"(r3) : "r"(addr))

#define MMA16816(d, a, b)                                                     \
    asm volatile("mma.sync.aligned.m16n8k16.row.col.f32.bf16.bf16.f32 "       \
                 "{%0,%1,%2,%3}, {%4,%5,%6,%7}, {%8,%9}, {%0,%1,%2,%3};"      \
                 : "+f"((d)[0]), "+f"((d)[1]), "+f"((d)[2]), "+f"((d)[3])     \
                 : "r"((a)[0]), "r"((a)[1]), "r"((a)[2]), "r"((a)[3]),        \
                   "r"((b)[0]), "r"((b)[1]))

__device__ __forceinline__ void split_bf(float v, __nv_bfloat16& h, __nv_bfloat16& l) {
    h = __float2bfloat16(v);
    l = __float2bfloat16(v - __bfloat162float(h));
}

// ================= shared GEMM mainloop =================
// acc[n_tok 128][m_feat 256] = sum over 3 hi/lo segments of X[n,k]*W[m,k]
__device__ __forceinline__ void gemm_mainloop(
    const __nv_bfloat16* __restrict__ Ah, const __nv_bfloat16* __restrict__ Al,
    const __nv_bfloat16* __restrict__ Bh, const __nv_bfloat16* __restrict__ Bl,
    int K, int tokBase, int featBase, char* smem, float (&c)[4][8][4]) {
    const uint32_t sb = smem_u32(smem);
    const int tid  = threadIdx.x;
    const int lane = tid & 31;
    const int wid  = tid >> 5;
    const int wm   = wid >> 2;          // 0..1
    const int wn   = wid & 3;           // 0..3
    const int lrow  = lane & 15;
    const int lhalf = lane >> 4;
    const int ktiles = K >> 6;
    const int TT = 3 * ktiles;

    // A loads: 2 threads per row, 4 x 16B each. B loads: 1 thread per row, 8 x 16B.
    const int arow = tid >> 1;
    const int acb  = (tid & 1) << 2;
    const size_t aoff = (size_t)(tokBase + arow) * K + acb * 8;
    const size_t boff = (size_t)(featBase + tid) * K;
    uint32_t asw[4], bsw[8];
#pragma unroll
    for (int j = 0; j < 4; j++) asw[j] = SWZ(arow * 128 + (acb + j) * 16);
#pragma unroll
    for (int j = 0; j < 8; j++) bsw[j] = SWZ(tid * 128 + j * 16);

    auto issue = [&](int tt) {
        const int seg  = tt / ktiles;
        const int koff = (tt - seg * ktiles) << 6;
        const __nv_bfloat16* Ap = ((seg == 1) ? Al : Ah) + aoff + koff;
        const __nv_bfloat16* Bp = ((seg == 2) ? Bl : Bh) + boff + koff;
        const uint32_t st = sb + (uint32_t)(tt % STAGES) * STAGE_BYTES;
#pragma unroll
        for (int j = 0; j < 4; j++)
            CPASYNC16(st + asw[j], (const void*)__cvta_generic_to_global(Ap + j * 8));
#pragma unroll
        for (int j = 0; j < 8; j++)
            CPASYNC16(st + STAGE_A + bsw[j], (const void*)__cvta_generic_to_global(Bp + j * 8));
    };

#pragma unroll
    for (int i = 0; i < 4; i++)
#pragma unroll
        for (int j = 0; j < 8; j++)
#pragma unroll
            for (int q = 0; q < 4; q++) c[i][j][q] = 0.f;

    issue(0); CPCOMMIT();
    issue(1); CPCOMMIT();

    for (int tt = 0; tt < TT; tt++) {
        CPWAIT1();
        __syncthreads();
        if (tt + 2 < TT) issue(tt + 2);
        CPCOMMIT();

        const uint32_t Ab = sb + (uint32_t)(tt % STAGES) * STAGE_BYTES;
        const uint32_t Bb = Ab + STAGE_A;
#pragma unroll
        for (int ks = 0; ks < 4; ks++) {
            const uint32_t kcol = (uint32_t)(ks * 2 + lhalf) * 16;
            uint32_t a[4][4];
#pragma unroll
            for (int mf = 0; mf < 4; mf++) {
                uint32_t ad = Ab + SWZ((uint32_t)(wm * 64 + mf * 16 + lrow) * 128 + kcol);
                LDSM4(a[mf][0], a[mf][1], a[mf][2], a[mf][3], ad);
            }
            uint32_t b[8][2];
#pragma unroll
            for (int g = 0; g < 4; g++) {
                uint32_t r0, r1, r2, r3;
                uint32_t bd = Bb + SWZ((uint32_t)(wn * 64 + g * 16 + lrow) * 128 + kcol);
                LDSM4(r0, r1, r2, r3, bd);
                b[2 * g][0] = r0;     b[2 * g][1] = r2;
                b[2 * g + 1][0] = r1; b[2 * g + 1][1] = r3;
            }
#pragma unroll
            for (int mf = 0; mf < 4; mf++)
#pragma unroll
                for (int nf = 0; nf < 8; nf++)
                    MMA16816(c[mf][nf], a[mf], b[nf]);
        }
    }
}

// Epilogue tile walk helper macro (variadic: body may contain commas).
// Body sees: r (token row), col (feature col), vx, vy (acc pair), idx.
#define EPI_WALK(Mfeat, ...)                                                  \
    do {                                                                      \
        const int lane = threadIdx.x & 31;                                    \
        const int wid  = threadIdx.x >> 5;                                    \
        const int rbase = tokBase + (wid >> 2) * 64 + (lane >> 2);            \
        const int cbase = featBase + (wid & 3) * 64 + (lane & 3) * 2;         \
        _Pragma("unroll")                                                     \
        for (int mf = 0; mf < 4; mf++) {                                      \
            _Pragma("unroll")                                                 \
            for (int nf = 0; nf < 8; nf++) {                                  \
                const int col = cbase + nf * 8;                               \
                _Pragma("unroll")                                             \
                for (int half = 0; half < 2; half++) {                        \
                    const int r = rbase + mf * 16 + half * 8;                 \
                    float vx = c[mf][nf][half * 2 + 0];                       \
                    float vy = c[mf][nf][half * 2 + 1];                       \
                    const size_t idx = (size_t)r * (Mfeat) + col;             \
                    __VA_ARGS__                                               \
                }                                                             \
            }                                                                 \
        }                                                                     \
    } while (0)

// ---- k/v/r projections fused via blockIdx.z (z=2 -> sigmoid) ----
__global__ __launch_bounds__(256)
void gemm_kvr(const __nv_bfloat16* __restrict__ xkh, const __nv_bfloat16* __restrict__ xkl,
              const __nv_bfloat16* __restrict__ xvh, const __nv_bfloat16* __restrict__ xvl,
              const __nv_bfloat16* __restrict__ xrh, const __nv_bfloat16* __restrict__ xrl,
              const __nv_bfloat16* __restrict__ wkh, const __nv_bfloat16* __restrict__ wkl,
              const __nv_bfloat16* __restrict__ wvh, const __nv_bfloat16* __restrict__ wvl,
              const __nv_bfloat16* __restrict__ wrh, const __nv_bfloat16* __restrict__ wrl,
              float* __restrict__ kb, float* __restrict__ vb, float* __restrict__ rb) {
    extern __shared__ char smem[];
    const int z = blockIdx.z;
    const int tokBase  = blockIdx.y << 7;
    const int featBase = blockIdx.x << 8;
    const __nv_bfloat16 *Ah, *Al, *Bh, *Bl;
    float* C;
    if (z == 0)      { Ah = xkh; Al = xkl; Bh = wkh; Bl = wkl; C = kb; }
    else if (z == 1) { Ah = xvh; Al = xvl; Bh = wvh; Bl = wvl; C = vb; }
    else             { Ah = xrh; Al = xrl; Bh = wrh; Bl = wrl; C = rb; }
    float c[4][8][4];
    gemm_mainloop(Ah, Al, Bh, Bl, HD, tokBase, featBase, smem, c);
    if (z == 2) {
        EPI_WALK(AD, {
            vx = 1.f / (1.f + __expf(-vx));
            vy = 1.f / (1.f + __expf(-vy));
            *(float2*)(C + idx) = make_float2(vx, vy);
        });
    } else {
        EPI_WALK(AD, { *(float2*)(C + idx) = make_float2(vx, vy); });
    }
}

// ---- FFN fwk (relu^2 -> bf16 split) + fwr (sigmoid) fused via blockIdx.x ----
__global__ __launch_bounds__(256)
void gemm_ffnpre(const __nv_bfloat16* __restrict__ xkh, const __nv_bfloat16* __restrict__ xkl,
                 const __nv_bfloat16* __restrict__ xrh, const __nv_bfloat16* __restrict__ xrl,
                 const __nv_bfloat16* __restrict__ fwkh, const __nv_bfloat16* __restrict__ fwkl,
                 const __nv_bfloat16* __restrict__ fwrh, const __nv_bfloat16* __restrict__ fwrl,
                 __nv_bfloat16* __restrict__ fkh, __nv_bfloat16* __restrict__ fkl,
                 float* __restrict__ rb) {
    extern __shared__ char smem[];
    const int bx = blockIdx.x;
    const int tokBase = blockIdx.y << 7;
    const bool isK = (bx < (FI / BN));
    const int featBase = (isK ? bx : bx - FI / BN) << 8;
    float c[4][8][4];
    if (isK) {
        gemm_mainloop(xkh, xkl, fwkh, fwkl, HD, tokBase, featBase, smem, c);
        EPI_WALK(FI, {
            vx = fmaxf(vx, 0.f); vx = vx * vx;
            vy = fmaxf(vy, 0.f); vy = vy * vy;
            __nv_bfloat16 hx, lx, hy, ly;
            split_bf(vx, hx, lx);
            split_bf(vy, hy, ly);
            *(__nv_bfloat162*)(fkh + idx) = __nv_bfloat162(hx, hy);
            *(__nv_bfloat162*)(fkl + idx) = __nv_bfloat162(lx, ly);
        });
    } else {
        gemm_mainloop(xrh, xrl, fwrh, fwrl, HD, tokBase, featBase, smem, c);
        EPI_WALK(HD, {
            vx = 1.f / (1.f + __expf(-vx));
            vy = 1.f / (1.f + __expf(-vy));
            *(float2*)(rb + idx) = make_float2(vx, vy);
        });
    }
}

// ---- generic accumulate GEMMs: EPI 3 (C+=v), EPI 4 (C+=aux*v) ----
template <int EPI>
__global__ __launch_bounds__(256)
void gemm_acc(const __nv_bfloat16* __restrict__ Ah, const __nv_bfloat16* __restrict__ Al,
              const __nv_bfloat16* __restrict__ Bh, const __nv_bfloat16* __restrict__ Bl,
              float* __restrict__ C, const float* __restrict__ aux, int Mfeat, int K) {
    extern __shared__ char smem[];
    const int tokBase  = blockIdx.y << 7;
    const int featBase = blockIdx.x << 8;
    float c[4][8][4];
    gemm_mainloop(Ah, Al, Bh, Bl, K, tokBase, featBase, smem, c);
    if (EPI == 3) {
        EPI_WALK(Mfeat, {
            float2 cur = *(float2*)(C + idx);
            cur.x += vx; cur.y += vy;
            *(float2*)(C + idx) = cur;
        });
    } else {
        EPI_WALK(Mfeat, {
            float2 cur = *(float2*)(C + idx);
            float2 a2 = *(const float2*)(aux + idx);
            cur.x = fmaf(a2.x, vx, cur.x);
            cur.y = fmaf(a2.y, vy, cur.y);
            *(float2*)(C + idx) = cur;
        });
    }
}

// ---------------- block reduction / layernorm ----------------
__device__ __forceinline__ float blkSum(float v) {
#pragma unroll
    for (int o = 16; o; o >>= 1) v += __shfl_xor_sync(0xffffffffu, v, o);
    __shared__ float sh[8];
    int w = threadIdx.x >> 5, l = threadIdx.x & 31;
    __syncthreads();
    if (l == 0) sh[w] = v;
    __syncthreads();
    float s = 0.f;
#pragma unroll
    for (int i = 0; i < 8; i++) s += sh[i];
    return s;
}

__device__ __forceinline__ float4 ln_reg(const float* __restrict__ row,
                                         const float* __restrict__ w,
                                         const float* __restrict__ b) {
    int t = threadIdx.x;
    float4 v = ((const float4*)row)[t];
    float s = blkSum(v.x + v.y + v.z + v.w);
    float mu = s * (1.f / HD);
    float dx = v.x - mu, dy = v.y - mu, dz = v.z - mu, dw = v.w - mu;
    float sq = blkSum(dx * dx + dy * dy + dz * dz + dw * dw);
    float rstd = rsqrtf(sq * (1.f / HD) + 1e-5f);
    float4 wv = ((const float4*)w)[t];
    float4 bv = ((const float4*)b)[t];
    float4 o;
    o.x = dx * rstd * wv.x + bv.x;
    o.y = dy * rstd * wv.y + bv.y;
    o.z = dz * rstd * wv.z + bv.z;
    o.w = dw * rstd * wv.w + bv.w;
    return o;
}

__global__ void ln_kernel(const float* __restrict__ in, const float* __restrict__ w,
                          const float* __restrict__ b, float* __restrict__ out) {
    size_t n = blockIdx.x;
    float4 o = ln_reg(in + n * HD, w, b);
    ((float4*)(out + n * HD))[threadIdx.x] = o;
}

__global__ void embed_ln_kernel(const int* __restrict__ ids, const float* __restrict__ emb,
                                const float* __restrict__ w, const float* __restrict__ b,
                                float* __restrict__ out) {
    size_t n = blockIdx.x;
    size_t idx = (size_t)ids[n];
    float4 o = ln_reg(emb + idx * HD, w, b);
    ((float4*)(out + n * HD))[threadIdx.x] = o;
}

// ---------------- fused LN + token-shift mix (emit bf16 hi/lo) ----------------
__device__ __forceinline__ void mix_store(float mc, float xc, float xp,
                                          __nv_bfloat16& hh, __nv_bfloat16& ll) {
    float v = mc * xc + (1.f - mc) * xp;
    split_bf(v, hh, ll);
}

__device__ __forceinline__ void store_pair4(__nv_bfloat16* __restrict__ H,
                                            __nv_bfloat16* __restrict__ L, size_t i,
                                            const float4& m4, const float4& xc,
                                            const float4& xp) {
    __nv_bfloat16 h0, l0, h1, l1, h2, l2, h3, l3;
    mix_store(m4.x, xc.x, xp.x, h0, l0);
    mix_store(m4.y, xc.y, xp.y, h1, l1);
    mix_store(m4.z, xc.z, xp.z, h2, l2);
    mix_store(m4.w, xc.w, xp.w, h3, l3);
    ((__nv_bfloat162*)(H + i))[0] = __nv_bfloat162(h0, h1);
    ((__nv_bfloat162*)(H + i))[1] = __nv_bfloat162(h2, h3);
    ((__nv_bfloat162*)(L + i))[0] = __nv_bfloat162(l0, l1);
    ((__nv_bfloat162*)(L + i))[1] = __nv_bfloat162(l2, l3);
}

__global__ void ln_mix3_kernel(const float* __restrict__ h,
                               const float* __restrict__ w, const float* __restrict__ b,
                               const float* __restrict__ mk, const float* __restrict__ mv,
                               const float* __restrict__ mr,
                               __nv_bfloat16* __restrict__ xkh, __nv_bfloat16* __restrict__ xkl,
                               __nv_bfloat16* __restrict__ xvh, __nv_bfloat16* __restrict__ xvl,
                               __nv_bfloat16* __restrict__ xrh, __nv_bfloat16* __restrict__ xrl) {
    size_t n = blockIdx.x;
    int t = (int)(n & (TSEQ - 1));
    float4 xc = ln_reg(h + n * HD, w, b);
    float4 xp = make_float4(0.f, 0.f, 0.f, 0.f);
    if (t) xp = ln_reg(h + (n - 1) * HD, w, b);
    size_t i = n * HD + (size_t)threadIdx.x * 4;
    store_pair4(xkh, xkl, i, ((const float4*)mk)[threadIdx.x], xc, xp);
    store_pair4(xvh, xvl, i, ((const float4*)mv)[threadIdx.x], xc, xp);
    store_pair4(xrh, xrl, i, ((const float4*)mr)[threadIdx.x], xc, xp);
}

__global__ void ln_mix2_kernel(const float* __restrict__ h,
                               const float* __restrict__ w, const float* __restrict__ b,
                               const float* __restrict__ mk, const float* __restrict__ mr,
                               __nv_bfloat16* __restrict__ xkh, __nv_bfloat16* __restrict__ xkl,
                               __nv_bfloat16* __restrict__ xrh, __nv_bfloat16* __restrict__ xrl) {
    size_t n = blockIdx.x;
    int t = (int)(n & (TSEQ - 1));
    float4 xc = ln_reg(h + n * HD, w, b);
    float4 xp = make_float4(0.f, 0.f, 0.f, 0.f);
    if (t) xp = ln_reg(h + (n - 1) * HD, w, b);
    size_t i = n * HD + (size_t)threadIdx.x * 4;
    store_pair4(xkh, xkl, i, ((const float4*)mk)[threadIdx.x], xc, xp);
    store_pair4(xrh, xrl, i, ((const float4*)mr)[threadIdx.x], xc, xp);
}

// ---------------- weight split fp32 -> bf16 hi/lo ----------------
__global__ void split_kernel(const float* __restrict__ src,
                             __nv_bfloat16* __restrict__ h, __nv_bfloat16* __restrict__ l,
                             int n4) {
    int i = (blockIdx.x * 256 + threadIdx.x);
    if (i >= n4) return;
    float4 v = ((const float4*)src)[i];
    __nv_bfloat16 h0, h1, h2, h3, l0, l1, l2, l3;
    split_bf(v.x, h0, l0); split_bf(v.y, h1, l1);
    split_bf(v.z, h2, l2); split_bf(v.w, h3, l3);
    __nv_bfloat162* Hp = (__nv_bfloat162*)(h + (size_t)i * 4);
    __nv_bfloat162* Lp = (__nv_bfloat162*)(l + (size_t)i * 4);
    Hp[0] = __nv_bfloat162(h0, h1); Hp[1] = __nv_bfloat162(h2, h3);
    Lp[0] = __nv_bfloat162(l0, l1); Lp[1] = __nv_bfloat162(l2, l3);
}

// ---------------- WKV scan (emits y hi/lo bf16) ----------------
__global__ void wkv_kernel(const float* __restrict__ tf, const float* __restrict__ td,
                           const float* __restrict__ k, const float* __restrict__ v,
                           const float* __restrict__ r,
                           __nv_bfloat16* __restrict__ yh, __nv_bfloat16* __restrict__ yl) {
    int laneid = blockIdx.x * 256 + threadIdx.x;
    int b = laneid >> 10;
    int a = laneid & (AD - 1);
    float u = tf[a];
    float w = -__expf(td[a]);
    float aa = 0.f, bb = 0.f, pp = -1e38f;
    size_t base = ((size_t)b * TSEQ) * AD + a;
    float kt = k[base], vt = v[base], rt = r[base];
    for (int t = 0; t < TSEQ; t++) {
        size_t off = base + (size_t)t * AD;
        float kn = 0.f, vn = 0.f, rn = 0.f;
        if (t + 1 < TSEQ) { kn = k[off + AD]; vn = v[off + AD]; rn = r[off + AD]; }
        float uk = u + kt;
        float q = fmaxf(pp, uk);
        float e1 = __expf(uk - q);
        float e2 = __expf(pp - q);
        float num = fmaf(aa, e2, e1 * vt);
        float den = fmaf(bb, e2, e1);
        float o = rt * (num / den);
        __nv_bfloat16 hh, ll;
        split_bf(o, hh, ll);
        yh[off] = hh; yl[off] = ll;
        float pw = pp + w;
        float q2 = fmaxf(pw, kt);
        float s1 = __expf(pw - q2);
        float s2 = __expf(kt - q2);
        aa = fmaf(s1, aa, s2 * vt);
        bb = fmaf(s1, bb, s2);
        pp = q2;
        kt = kn; vt = vn; rt = rn;
    }
}

// ---------------- orchestration ----------------
extern "C" void kernel_launch(void* const* d_in, const int* in_sizes, int n_in,
                              void* d_out, int out_size) {
    const int*   ids   = (const int*)d_in[0];
    const float* emb   = (const float*)d_in[1];
    const float* prew  = (const float*)d_in[2];
    const float* preb  = (const float*)d_in[3];
    const float* postw = (const float*)d_in[4];
    const float* postb = (const float*)d_in[5];
    const float* ln1w  = (const float*)d_in[6];
    const float* ln1b  = (const float*)d_in[7];
    const float* ln2w  = (const float*)d_in[8];
    const float* ln2b  = (const float*)d_in[9];
    const float* mxk   = (const float*)d_in[10];
    const float* mxv   = (const float*)d_in[11];
    const float* mxr   = (const float*)d_in[12];
    const float* wk    = (const float*)d_in[13];
    const float* wv    = (const float*)d_in[14];
    const float* wr    = (const float*)d_in[15];
    const float* wo    = (const float*)d_in[16];
    const float* tdec  = (const float*)d_in[17];
    const float* tfir  = (const float*)d_in[18];
    const float* fmk   = (const float*)d_in[19];
    const float* fmr   = (const float*)d_in[20];
    const float* fwk   = (const float*)d_in[21];
    const float* fwr   = (const float*)d_in[22];
    const float* fwv   = (const float*)d_in[23];
    float* out = (float*)d_out;

    void* p;
    cudaGetSymbolAddress(&p, g_h);    float* h  = (float*)p;
    cudaGetSymbolAddress(&p, g_k);    float* kb = (float*)p;
    cudaGetSymbolAddress(&p, g_v);    float* vb = (float*)p;
    cudaGetSymbolAddress(&p, g_r);    float* rb = (float*)p;
    cudaGetSymbolAddress(&p, g_xkh);  __nv_bfloat16* xkh = (__nv_bfloat16*)p;
    cudaGetSymbolAddress(&p, g_xkl);  __nv_bfloat16* xkl = (__nv_bfloat16*)p;
    cudaGetSymbolAddress(&p, g_xvh);  __nv_bfloat16* xvh = (__nv_bfloat16*)p;
    cudaGetSymbolAddress(&p, g_xvl);  __nv_bfloat16* xvl = (__nv_bfloat16*)p;
    cudaGetSymbolAddress(&p, g_xrh);  __nv_bfloat16* xrh = (__nv_bfloat16*)p;
    cudaGetSymbolAddress(&p, g_xrl);  __nv_bfloat16* xrl = (__nv_bfloat16*)p;
    cudaGetSymbolAddress(&p, g_yh);   __nv_bfloat16* yh  = (__nv_bfloat16*)p;
    cudaGetSymbolAddress(&p, g_yl);   __nv_bfloat16* yl  = (__nv_bfloat16*)p;
    cudaGetSymbolAddress(&p, g_fkh);  __nv_bfloat16* fkh = (__nv_bfloat16*)p;
    cudaGetSymbolAddress(&p, g_fkl);  __nv_bfloat16* fkl = (__nv_bfloat16*)p;
    cudaGetSymbolAddress(&p, g_wkh);  __nv_bfloat16* wkh = (__nv_bfloat16*)p;
    cudaGetSymbolAddress(&p, g_wkl);  __nv_bfloat16* wkl = (__nv_bfloat16*)p;
    cudaGetSymbolAddress(&p, g_wvh);  __nv_bfloat16* wvh = (__nv_bfloat16*)p;
    cudaGetSymbolAddress(&p, g_wvl);  __nv_bfloat16* wvl = (__nv_bfloat16*)p;
    cudaGetSymbolAddress(&p, g_wrh);  __nv_bfloat16* wrh = (__nv_bfloat16*)p;
    cudaGetSymbolAddress(&p, g_wrl);  __nv_bfloat16* wrl = (__nv_bfloat16*)p;
    cudaGetSymbolAddress(&p, g_woh);  __nv_bfloat16* woh = (__nv_bfloat16*)p;
    cudaGetSymbolAddress(&p, g_wol);  __nv_bfloat16* wol = (__nv_bfloat16*)p;
    cudaGetSymbolAddress(&p, g_fwkh); __nv_bfloat16* fwkh = (__nv_bfloat16*)p;
    cudaGetSymbolAddress(&p, g_fwkl); __nv_bfloat16* fwkl = (__nv_bfloat16*)p;
    cudaGetSymbolAddress(&p, g_fwrh); __nv_bfloat16* fwrh = (__nv_bfloat16*)p;
    cudaGetSymbolAddress(&p, g_fwrl); __nv_bfloat16* fwrl = (__nv_bfloat16*)p;
    cudaGetSymbolAddress(&p, g_fwvh); __nv_bfloat16* fwvh = (__nv_bfloat16*)p;
    cudaGetSymbolAddress(&p, g_fwvl); __nv_bfloat16* fwvl = (__nv_bfloat16*)p;

    cudaFuncSetAttribute(gemm_kvr, cudaFuncAttributeMaxDynamicSharedMemorySize, SMEM_SZ);
    cudaFuncSetAttribute(gemm_ffnpre, cudaFuncAttributeMaxDynamicSharedMemorySize, SMEM_SZ);
    cudaFuncSetAttribute(gemm_acc<3>, cudaFuncAttributeMaxDynamicSharedMemorySize, SMEM_SZ);
    cudaFuncSetAttribute(gemm_acc<4>, cudaFuncAttributeMaxDynamicSharedMemorySize, SMEM_SZ);

    // ---- weight splits (once per launch) ----
    const int nW  = NL * AD * HD;
    const int nWI = NL * FI * HD;
    split_kernel<<<nW / 1024, 256>>>(wk, wkh, wkl, nW / 4);
    split_kernel<<<nW / 1024, 256>>>(wv, wvh, wvl, nW / 4);
    split_kernel<<<nW / 1024, 256>>>(wr, wrh, wrl, nW / 4);
    split_kernel<<<nW / 1024, 256>>>(wo, woh, wol, nW / 4);
    split_kernel<<<nWI / 1024, 256>>>(fwk, fwkh, fwkl, nWI / 4);
    split_kernel<<<nW / 1024, 256>>>(fwr, fwrh, fwrl, nW / 4);
    split_kernel<<<nWI / 1024, 256>>>(fwv, fwvh, fwvl, nWI / 4);

    const dim3 gKVR(HD / BN, NTOK / BM, 3);          // (4, 64, 3)
    const dim3 gH(HD / BN, NTOK / BM);               // (4, 64)
    const dim3 gFFN(FI / BN + HD / BN, NTOK / BM);   // (20, 64)

    embed_ln_kernel<<<NTOK, 256>>>(ids, emb, prew, preb, h);

    for (int i = 0; i < NL; i++) {
        const size_t oW  = (size_t)i * AD * HD;
        const size_t oWI = (size_t)i * FI * HD;
        // ---- attention / time mix ----
        ln_mix3_kernel<<<NTOK, 256>>>(h, ln1w + i * HD, ln1b + i * HD,
                                      mxk + i * HD, mxv + i * HD, mxr + i * HD,
                                      xkh, xkl, xvh, xvl, xrh, xrl);
        gemm_kvr<<<gKVR, 256, SMEM_SZ>>>(xkh, xkl, xvh, xvl, xrh, xrl,
                                         wkh + oW, wkl + oW, wvh + oW, wvl + oW,
                                         wrh + oW, wrl + oW, kb, vb, rb);
        wkv_kernel<<<NBB * AD / 256, 256>>>(tfir + i * AD, tdec + i * AD,
                                            kb, vb, rb, yh, yl);
        gemm_acc<3><<<gH, 256, SMEM_SZ>>>(yh, yl, woh + oW, wol + oW,
                                          h, nullptr, HD, AD);
        // ---- ffn / channel mix ----
        ln_mix2_kernel<<<NTOK, 256>>>(h, ln2w + i * HD, ln2b + i * HD,
                                      fmk + i * HD, fmr + i * HD,
                                      xkh, xkl, xrh, xrl);
        gemm_ffnpre<<<gFFN, 256, SMEM_SZ>>>(xkh, xkl, xrh, xrl,
                                            fwkh + oWI, fwkl + oWI,
                                            fwrh + oW, fwrl + oW,
                                            fkh, fkl, rb);
        gemm_acc<4><<<gH, 256, SMEM_SZ>>>(fkh, fkl, fwvh + oWI, fwvl + oWI,
                                          h, rb, HD, FI);
    }

    ln_kernel<<<NTOK, 256>>>(h, postw, postb, out);
}

// round 13
// speedup vs baseline: 1.2017x; 1.2017x over previous
#include <cuda_runtime.h>
#include <cuda_bf16.h>
#include <cstdint>

// ---------------- problem constants ----------------
#define NL    6
#define HD    1024
#define AD    1024
#define FI    4096
#define NBB   4
#define TSEQ  2048
#define NTOK  (NBB * TSEQ)     // 8192 tokens

// ---------------- GEMM tile constants (R5-proven 128x128) ----------------
#define BM 128
#define BN 128
#define BK 64                  // bf16 elems per K tile (128B rows = SW128 atom)
#define STAGES 3
#define STAGE_A 16384
#define STAGE_B 16384
#define STAGE_BYTES (STAGE_A + STAGE_B)      // 32768
#define SMEM_SZ (STAGES * STAGE_BYTES)       // 98304 -> 2 CTAs/SM fits 228KB

#define SWZ(o) ((o) ^ ((((uint32_t)(o)) >> 3) & 0x70))

// ---------------- persistent scratch ----------------
__device__ __align__(16) float g_h[NTOK * HD];
__device__ __align__(16) float g_k[NTOK * AD];
__device__ __align__(16) float g_v[NTOK * AD];
__device__ __align__(16) float g_r[NTOK * AD];
__device__ __align__(16) __nv_bfloat16 g_xkh[NTOK * HD], g_xkl[NTOK * HD];
__device__ __align__(16) __nv_bfloat16 g_xvh[NTOK * HD], g_xvl[NTOK * HD];
__device__ __align__(16) __nv_bfloat16 g_xrh[NTOK * HD], g_xrl[NTOK * HD];
__device__ __align__(16) __nv_bfloat16 g_yh[NTOK * AD], g_yl[NTOK * AD];
__device__ __align__(16) __nv_bfloat16 g_fkh[NTOK * FI], g_fkl[NTOK * FI];
// weight hi/lo
__device__ __align__(16) __nv_bfloat16 g_wkh[NL * AD * HD], g_wkl[NL * AD * HD];
__device__ __align__(16) __nv_bfloat16 g_wvh[NL * AD * HD], g_wvl[NL * AD * HD];
__device__ __align__(16) __nv_bfloat16 g_wrh[NL * AD * HD], g_wrl[NL * AD * HD];
__device__ __align__(16) __nv_bfloat16 g_woh[NL * HD * AD], g_wol[NL * HD * AD];
__device__ __align__(16) __nv_bfloat16 g_fwkh[NL * FI * HD], g_fwkl[NL * FI * HD];
__device__ __align__(16) __nv_bfloat16 g_fwrh[NL * HD * HD], g_fwrl[NL * HD * HD];
__device__ __align__(16) __nv_bfloat16 g_fwvh[NL * HD * FI], g_fwvl[NL * HD * FI];

// ---------------- PTX helpers (portable sm_80+ features only) ----------------
__device__ __forceinline__ uint32_t smem_u32(const void* p) {
    uint32_t a;
    asm("{ .reg .u64 t; cvta.to.shared.u64 t, %1; cvt.u32.u64 %0, t; }"
        : "=r"(a) : "l"(p));
    return a;
}

#define CPASYNC16(saddr, gptr)                                                \
    asm volatile("cp.async.cg.shared.global [%0], [%1], 16;"                  \
                 :: "r"(saddr), "l"(gptr))
#define CPCOMMIT() asm volatile("cp.async.commit_group;" ::: "memory")
#define CPWAIT1()  asm volatile("cp.async.wait_group 1;" ::: "memory")

#define LDSM4(r0, r1, r2, r3, addr)                                           \
    asm volatile("ldmatrix.sync.aligned.m8n8.x4.shared.b16 {%0,%1,%2,%3}, [%4];" \
                 : "=r"(r0), "=r"(r1), "=r"(r2), "=r"(r3) : "r"(addr))

#define MMA16816(d, a, b)                                                     \
    asm volatile("mma.sync.aligned.m16n8k16.row.col.f32.bf16.bf16.f32 "       \
                 "{%0,%1,%2,%3}, {%4,%5,%6,%7}, {%8,%9}, {%0,%1,%2,%3};"      \
                 : "+f"((d)[0]), "+f"((d)[1]), "+f"((d)[2]), "+f"((d)[3])     \
                 : "r"((a)[0]), "r"((a)[1]), "r"((a)[2]), "r"((a)[3]),        \
                   "r"((b)[0]), "r"((b)[1]))

__device__ __forceinline__ void split_bf(float v, __nv_bfloat16& h, __nv_bfloat16& l) {
    h = __float2bfloat16(v);
    l = __float2bfloat16(v - __bfloat162float(h));
}

// ================= shared GEMM mainloop (R5 tile) =================
// acc[n_tok 128][m_feat 128] = sum over 3 hi/lo segments of X[n,k]*W[m,k]
__device__ __forceinline__ void gemm_mainloop(
    const __nv_bfloat16* __restrict__ Ah, const __nv_bfloat16* __restrict__ Al,
    const __nv_bfloat16* __restrict__ Bh, const __nv_bfloat16* __restrict__ Bl,
    int K, int tokBase, int featBase, char* smem, float (&c)[4][4][4]) {
    const uint32_t sb = smem_u32(smem);
    const int tid  = threadIdx.x;
    const int lane = tid & 31;
    const int wid  = tid >> 5;
    const int wm   = wid >> 2;          // 0..1
    const int wn   = wid & 3;           // 0..3
    const int lrow  = lane & 15;
    const int lhalf = lane >> 4;
    const int ktiles = K >> 6;
    const int TT = 3 * ktiles;

    // Loads: 2 threads per row, 4 x 16B chunks each, for both A and B.
    const int ldrow = tid >> 1;          // 0..127
    const int ldcb  = (tid & 1) << 2;    // chunk base 0 or 4
    const size_t aoff = (size_t)(tokBase + ldrow) * K + ldcb * 8;
    const size_t boff = (size_t)(featBase + ldrow) * K + ldcb * 8;
    uint32_t smoff[4];
#pragma unroll
    for (int j = 0; j < 4; j++)
        smoff[j] = SWZ(ldrow * 128 + (ldcb + j) * 16);

    auto issue = [&](int tt) {
        const int seg  = tt / ktiles;
        const int koff = (tt - seg * ktiles) << 6;
        const __nv_bfloat16* Ap = ((seg == 1) ? Al : Ah) + aoff + koff;
        const __nv_bfloat16* Bp = ((seg == 2) ? Bl : Bh) + boff + koff;
        const uint32_t st = sb + (uint32_t)(tt % STAGES) * STAGE_BYTES;
#pragma unroll
        for (int j = 0; j < 4; j++) {
            CPASYNC16(st + smoff[j], (const void*)__cvta_generic_to_global(Ap + j * 8));
            CPASYNC16(st + STAGE_A + smoff[j], (const void*)__cvta_generic_to_global(Bp + j * 8));
        }
    };

#pragma unroll
    for (int i = 0; i < 4; i++)
#pragma unroll
        for (int j = 0; j < 4; j++)
#pragma unroll
            for (int q = 0; q < 4; q++) c[i][j][q] = 0.f;

    issue(0); CPCOMMIT();
    issue(1); CPCOMMIT();

    for (int tt = 0; tt < TT; tt++) {
        CPWAIT1();
        __syncthreads();
        if (tt + 2 < TT) issue(tt + 2);
        CPCOMMIT();

        const uint32_t Ab = sb + (uint32_t)(tt % STAGES) * STAGE_BYTES;
        const uint32_t Bb = Ab + STAGE_A;
#pragma unroll
        for (int ks = 0; ks < 4; ks++) {
            const uint32_t kcol = (uint32_t)(ks * 2 + lhalf) * 16;
            uint32_t a[4][4];
#pragma unroll
            for (int mf = 0; mf < 4; mf++) {
                uint32_t ad = Ab + SWZ((uint32_t)(wm * 64 + mf * 16 + lrow) * 128 + kcol);
                LDSM4(a[mf][0], a[mf][1], a[mf][2], a[mf][3], ad);
            }
            uint32_t b[4][2];
#pragma unroll
            for (int g = 0; g < 2; g++) {
                uint32_t r0, r1, r2, r3;
                uint32_t bd = Bb + SWZ((uint32_t)(wn * 32 + g * 16 + lrow) * 128 + kcol);
                LDSM4(r0, r1, r2, r3, bd);
                b[2 * g][0] = r0;     b[2 * g][1] = r2;
                b[2 * g + 1][0] = r1; b[2 * g + 1][1] = r3;
            }
#pragma unroll
            for (int mf = 0; mf < 4; mf++)
#pragma unroll
                for (int nf = 0; nf < 4; nf++)
                    MMA16816(c[mf][nf], a[mf], b[nf]);
        }
    }
}

// Epilogue tile walk helper macro (variadic: body may contain commas).
// Body sees: r (token row), col (feature col), vx, vy (acc pair), idx.
#define EPI_WALK(Mfeat, ...)                                                  \
    do {                                                                      \
        const int lane = threadIdx.x & 31;                                    \
        const int wid  = threadIdx.x >> 5;                                    \
        const int rbase = tokBase + (wid >> 2) * 64 + (lane >> 2);            \
        const int cbase = featBase + (wid & 3) * 32 + (lane & 3) * 2;         \
        _Pragma("unroll")                                                     \
        for (int mf = 0; mf < 4; mf++) {                                      \
            _Pragma("unroll")                                                 \
            for (int nf = 0; nf < 4; nf++) {                                  \
                const int col = cbase + nf * 8;                               \
                _Pragma("unroll")                                             \
                for (int half = 0; half < 2; half++) {                        \
                    const int r = rbase + mf * 16 + half * 8;                 \
                    float vx = c[mf][nf][half * 2 + 0];                       \
                    float vy = c[mf][nf][half * 2 + 1];                       \
                    const size_t idx = (size_t)r * (Mfeat) + col;             \
                    __VA_ARGS__                                               \
                }                                                             \
            }                                                                 \
        }                                                                     \
    } while (0)

// ---- k/v/r projections fused via blockIdx.z (z=2 -> sigmoid) ----
__global__ __launch_bounds__(256, 2)
void gemm_kvr(const __nv_bfloat16* __restrict__ xkh, const __nv_bfloat16* __restrict__ xkl,
              const __nv_bfloat16* __restrict__ xvh, const __nv_bfloat16* __restrict__ xvl,
              const __nv_bfloat16* __restrict__ xrh, const __nv_bfloat16* __restrict__ xrl,
              const __nv_bfloat16* __restrict__ wkh, const __nv_bfloat16* __restrict__ wkl,
              const __nv_bfloat16* __restrict__ wvh, const __nv_bfloat16* __restrict__ wvl,
              const __nv_bfloat16* __restrict__ wrh, const __nv_bfloat16* __restrict__ wrl,
              float* __restrict__ kb, float* __restrict__ vb, float* __restrict__ rb) {
    extern __shared__ char smem[];
    const int z = blockIdx.z;
    const int tokBase  = blockIdx.y << 7;
    const int featBase = blockIdx.x << 7;
    const __nv_bfloat16 *Ah, *Al, *Bh, *Bl;
    float* C;
    if (z == 0)      { Ah = xkh; Al = xkl; Bh = wkh; Bl = wkl; C = kb; }
    else if (z == 1) { Ah = xvh; Al = xvl; Bh = wvh; Bl = wvl; C = vb; }
    else             { Ah = xrh; Al = xrl; Bh = wrh; Bl = wrl; C = rb; }
    float c[4][4][4];
    gemm_mainloop(Ah, Al, Bh, Bl, HD, tokBase, featBase, smem, c);
    if (z == 2) {
        EPI_WALK(AD, {
            vx = 1.f / (1.f + __expf(-vx));
            vy = 1.f / (1.f + __expf(-vy));
            *(float2*)(C + idx) = make_float2(vx, vy);
        });
    } else {
        EPI_WALK(AD, { *(float2*)(C + idx) = make_float2(vx, vy); });
    }
}

// ---- FFN fwk (relu^2 -> bf16 split) + fwr (sigmoid) fused via blockIdx.x ----
__global__ __launch_bounds__(256, 2)
void gemm_ffnpre(const __nv_bfloat16* __restrict__ xkh, const __nv_bfloat16* __restrict__ xkl,
                 const __nv_bfloat16* __restrict__ xrh, const __nv_bfloat16* __restrict__ xrl,
                 const __nv_bfloat16* __restrict__ fwkh, const __nv_bfloat16* __restrict__ fwkl,
                 const __nv_bfloat16* __restrict__ fwrh, const __nv_bfloat16* __restrict__ fwrl,
                 __nv_bfloat16* __restrict__ fkh, __nv_bfloat16* __restrict__ fkl,
                 float* __restrict__ rb) {
    extern __shared__ char smem[];
    const int bx = blockIdx.x;
    const int tokBase = blockIdx.y << 7;
    const bool isK = (bx < (FI / BN));
    const int featBase = (isK ? bx : bx - FI / BN) << 7;
    float c[4][4][4];
    if (isK) {
        gemm_mainloop(xkh, xkl, fwkh, fwkl, HD, tokBase, featBase, smem, c);
        EPI_WALK(FI, {
            vx = fmaxf(vx, 0.f); vx = vx * vx;
            vy = fmaxf(vy, 0.f); vy = vy * vy;
            __nv_bfloat16 hx, lx, hy, ly;
            split_bf(vx, hx, lx);
            split_bf(vy, hy, ly);
            *(__nv_bfloat162*)(fkh + idx) = __nv_bfloat162(hx, hy);
            *(__nv_bfloat162*)(fkl + idx) = __nv_bfloat162(lx, ly);
        });
    } else {
        gemm_mainloop(xrh, xrl, fwrh, fwrl, HD, tokBase, featBase, smem, c);
        EPI_WALK(HD, {
            vx = 1.f / (1.f + __expf(-vx));
            vy = 1.f / (1.f + __expf(-vy));
            *(float2*)(rb + idx) = make_float2(vx, vy);
        });
    }
}

// ---- generic accumulate GEMMs: EPI 3 (C+=v), EPI 4 (C+=aux*v) ----
template <int EPI>
__global__ __launch_bounds__(256, 2)
void gemm_acc(const __nv_bfloat16* __restrict__ Ah, const __nv_bfloat16* __restrict__ Al,
              const __nv_bfloat16* __restrict__ Bh, const __nv_bfloat16* __restrict__ Bl,
              float* __restrict__ C, const float* __restrict__ aux, int Mfeat, int K) {
    extern __shared__ char smem[];
    const int tokBase  = blockIdx.y << 7;
    const int featBase = blockIdx.x << 7;
    float c[4][4][4];
    gemm_mainloop(Ah, Al, Bh, Bl, K, tokBase, featBase, smem, c);
    if (EPI == 3) {
        EPI_WALK(Mfeat, {
            float2 cur = *(float2*)(C + idx);
            cur.x += vx; cur.y += vy;
            *(float2*)(C + idx) = cur;
        });
    } else {
        EPI_WALK(Mfeat, {
            float2 cur = *(float2*)(C + idx);
            float2 a2 = *(const float2*)(aux + idx);
            cur.x = fmaf(a2.x, vx, cur.x);
            cur.y = fmaf(a2.y, vy, cur.y);
            *(float2*)(C + idx) = cur;
        });
    }
}

// ---------------- block reduction / layernorm ----------------
__device__ __forceinline__ float blkSum(float v) {
#pragma unroll
    for (int o = 16; o; o >>= 1) v += __shfl_xor_sync(0xffffffffu, v, o);
    __shared__ float sh[8];
    int w = threadIdx.x >> 5, l = threadIdx.x & 31;
    __syncthreads();
    if (l == 0) sh[w] = v;
    __syncthreads();
    float s = 0.f;
#pragma unroll
    for (int i = 0; i < 8; i++) s += sh[i];
    return s;
}

__device__ __forceinline__ float4 ln_reg(const float* __restrict__ row,
                                         const float* __restrict__ w,
                                         const float* __restrict__ b) {
    int t = threadIdx.x;
    float4 v = ((const float4*)row)[t];
    float s = blkSum(v.x + v.y + v.z + v.w);
    float mu = s * (1.f / HD);
    float dx = v.x - mu, dy = v.y - mu, dz = v.z - mu, dw = v.w - mu;
    float sq = blkSum(dx * dx + dy * dy + dz * dz + dw * dw);
    float rstd = rsqrtf(sq * (1.f / HD) + 1e-5f);
    float4 wv = ((const float4*)w)[t];
    float4 bv = ((const float4*)b)[t];
    float4 o;
    o.x = dx * rstd * wv.x + bv.x;
    o.y = dy * rstd * wv.y + bv.y;
    o.z = dz * rstd * wv.z + bv.z;
    o.w = dw * rstd * wv.w + bv.w;
    return o;
}

__global__ void ln_kernel(const float* __restrict__ in, const float* __restrict__ w,
                          const float* __restrict__ b, float* __restrict__ out) {
    size_t n = blockIdx.x;
    float4 o = ln_reg(in + n * HD, w, b);
    ((float4*)(out + n * HD))[threadIdx.x] = o;
}

__global__ void embed_ln_kernel(const int* __restrict__ ids, const float* __restrict__ emb,
                                const float* __restrict__ w, const float* __restrict__ b,
                                float* __restrict__ out) {
    size_t n = blockIdx.x;
    size_t idx = (size_t)ids[n];
    float4 o = ln_reg(emb + idx * HD, w, b);
    ((float4*)(out + n * HD))[threadIdx.x] = o;
}

// ---------------- fused LN + token-shift mix (emit bf16 hi/lo) ----------------
__device__ __forceinline__ void mix_store(float mc, float xc, float xp,
                                          __nv_bfloat16& hh, __nv_bfloat16& ll) {
    float v = mc * xc + (1.f - mc) * xp;
    split_bf(v, hh, ll);
}

__device__ __forceinline__ void store_pair4(__nv_bfloat16* __restrict__ H,
                                            __nv_bfloat16* __restrict__ L, size_t i,
                                            const float4& m4, const float4& xc,
                                            const float4& xp) {
    __nv_bfloat16 h0, l0, h1, l1, h2, l2, h3, l3;
    mix_store(m4.x, xc.x, xp.x, h0, l0);
    mix_store(m4.y, xc.y, xp.y, h1, l1);
    mix_store(m4.z, xc.z, xp.z, h2, l2);
    mix_store(m4.w, xc.w, xp.w, h3, l3);
    ((__nv_bfloat162*)(H + i))[0] = __nv_bfloat162(h0, h1);
    ((__nv_bfloat162*)(H + i))[1] = __nv_bfloat162(h2, h3);
    ((__nv_bfloat162*)(L + i))[0] = __nv_bfloat162(l0, l1);
    ((__nv_bfloat162*)(L + i))[1] = __nv_bfloat162(l2, l3);
}

__global__ void ln_mix3_kernel(const float* __restrict__ h,
                               const float* __restrict__ w, const float* __restrict__ b,
                               const float* __restrict__ mk, const float* __restrict__ mv,
                               const float* __restrict__ mr,
                               __nv_bfloat16* __restrict__ xkh, __nv_bfloat16* __restrict__ xkl,
                               __nv_bfloat16* __restrict__ xvh, __nv_bfloat16* __restrict__ xvl,
                               __nv_bfloat16* __restrict__ xrh, __nv_bfloat16* __restrict__ xrl) {
    size_t n = blockIdx.x;
    int t = (int)(n & (TSEQ - 1));
    float4 xc = ln_reg(h + n * HD, w, b);
    float4 xp = make_float4(0.f, 0.f, 0.f, 0.f);
    if (t) xp = ln_reg(h + (n - 1) * HD, w, b);
    size_t i = n * HD + (size_t)threadIdx.x * 4;
    store_pair4(xkh, xkl, i, ((const float4*)mk)[threadIdx.x], xc, xp);
    store_pair4(xvh, xvl, i, ((const float4*)mv)[threadIdx.x], xc, xp);
    store_pair4(xrh, xrl, i, ((const float4*)mr)[threadIdx.x], xc, xp);
}

__global__ void ln_mix2_kernel(const float* __restrict__ h,
                               const float* __restrict__ w, const float* __restrict__ b,
                               const float* __restrict__ mk, const float* __restrict__ mr,
                               __nv_bfloat16* __restrict__ xkh, __nv_bfloat16* __restrict__ xkl,
                               __nv_bfloat16* __restrict__ xrh, __nv_bfloat16* __restrict__ xrl) {
    size_t n = blockIdx.x;
    int t = (int)(n & (TSEQ - 1));
    float4 xc = ln_reg(h + n * HD, w, b);
    float4 xp = make_float4(0.f, 0.f, 0.f, 0.f);
    if (t) xp = ln_reg(h + (n - 1) * HD, w, b);
    size_t i = n * HD + (size_t)threadIdx.x * 4;
    store_pair4(xkh, xkl, i, ((const float4*)mk)[threadIdx.x], xc, xp);
    store_pair4(xrh, xrl, i, ((const float4*)mr)[threadIdx.x], xc, xp);
}

// ---------------- weight split fp32 -> bf16 hi/lo ----------------
__global__ void split_kernel(const float* __restrict__ src,
                             __nv_bfloat16* __restrict__ h, __nv_bfloat16* __restrict__ l,
                             int n4) {
    int i = (blockIdx.x * 256 + threadIdx.x);
    if (i >= n4) return;
    float4 v = ((const float4*)src)[i];
    __nv_bfloat16 h0, h1, h2, h3, l0, l1, l2, l3;
    split_bf(v.x, h0, l0); split_bf(v.y, h1, l1);
    split_bf(v.z, h2, l2); split_bf(v.w, h3, l3);
    __nv_bfloat162* Hp = (__nv_bfloat162*)(h + (size_t)i * 4);
    __nv_bfloat162* Lp = (__nv_bfloat162*)(l + (size_t)i * 4);
    Hp[0] = __nv_bfloat162(h0, h1); Hp[1] = __nv_bfloat162(h2, h3);
    Lp[0] = __nv_bfloat162(l0, l1); Lp[1] = __nv_bfloat162(l2, l3);
}

// ---------------- WKV scan (emits y hi/lo bf16) ----------------
__global__ void wkv_kernel(const float* __restrict__ tf, const float* __restrict__ td,
                           const float* __restrict__ k, const float* __restrict__ v,
                           const float* __restrict__ r,
                           __nv_bfloat16* __restrict__ yh, __nv_bfloat16* __restrict__ yl) {
    int laneid = blockIdx.x * 256 + threadIdx.x;
    int b = laneid >> 10;
    int a = laneid & (AD - 1);
    float u = tf[a];
    float w = -__expf(td[a]);
    float aa = 0.f, bb = 0.f, pp = -1e38f;
    size_t base = ((size_t)b * TSEQ) * AD + a;
    float kt = k[base], vt = v[base], rt = r[base];
    for (int t = 0; t < TSEQ; t++) {
        size_t off = base + (size_t)t * AD;
        float kn = 0.f, vn = 0.f, rn = 0.f;
        if (t + 1 < TSEQ) { kn = k[off + AD]; vn = v[off + AD]; rn = r[off + AD]; }
        float uk = u + kt;
        float q = fmaxf(pp, uk);
        float e1 = __expf(uk - q);
        float e2 = __expf(pp - q);
        float num = fmaf(aa, e2, e1 * vt);
        float den = fmaf(bb, e2, e1);
        float o = rt * (num / den);
        __nv_bfloat16 hh, ll;
        split_bf(o, hh, ll);
        yh[off] = hh; yl[off] = ll;
        float pw = pp + w;
        float q2 = fmaxf(pw, kt);
        float s1 = __expf(pw - q2);
        float s2 = __expf(kt - q2);
        aa = fmaf(s1, aa, s2 * vt);
        bb = fmaf(s1, bb, s2);
        pp = q2;
        kt = kn; vt = vn; rt = rn;
    }
}

// ---------------- orchestration ----------------
extern "C" void kernel_launch(void* const* d_in, const int* in_sizes, int n_in,
                              void* d_out, int out_size) {
    const int*   ids   = (const int*)d_in[0];
    const float* emb   = (const float*)d_in[1];
    const float* prew  = (const float*)d_in[2];
    const float* preb  = (const float*)d_in[3];
    const float* postw = (const float*)d_in[4];
    const float* postb = (const float*)d_in[5];
    const float* ln1w  = (const float*)d_in[6];
    const float* ln1b  = (const float*)d_in[7];
    const float* ln2w  = (const float*)d_in[8];
    const float* ln2b  = (const float*)d_in[9];
    const float* mxk   = (const float*)d_in[10];
    const float* mxv   = (const float*)d_in[11];
    const float* mxr   = (const float*)d_in[12];
    const float* wk    = (const float*)d_in[13];
    const float* wv    = (const float*)d_in[14];
    const float* wr    = (const float*)d_in[15];
    const float* wo    = (const float*)d_in[16];
    const float* tdec  = (const float*)d_in[17];
    const float* tfir  = (const float*)d_in[18];
    const float* fmk   = (const float*)d_in[19];
    const float* fmr   = (const float*)d_in[20];
    const float* fwk   = (const float*)d_in[21];
    const float* fwr   = (const float*)d_in[22];
    const float* fwv   = (const float*)d_in[23];
    float* out = (float*)d_out;

    void* p;
    cudaGetSymbolAddress(&p, g_h);    float* h  = (float*)p;
    cudaGetSymbolAddress(&p, g_k);    float* kb = (float*)p;
    cudaGetSymbolAddress(&p, g_v);    float* vb = (float*)p;
    cudaGetSymbolAddress(&p, g_r);    float* rb = (float*)p;
    cudaGetSymbolAddress(&p, g_xkh);  __nv_bfloat16* xkh = (__nv_bfloat16*)p;
    cudaGetSymbolAddress(&p, g_xkl);  __nv_bfloat16* xkl = (__nv_bfloat16*)p;
    cudaGetSymbolAddress(&p, g_xvh);  __nv_bfloat16* xvh = (__nv_bfloat16*)p;
    cudaGetSymbolAddress(&p, g_xvl);  __nv_bfloat16* xvl = (__nv_bfloat16*)p;
    cudaGetSymbolAddress(&p, g_xrh);  __nv_bfloat16* xrh = (__nv_bfloat16*)p;
    cudaGetSymbolAddress(&p, g_xrl);  __nv_bfloat16* xrl = (__nv_bfloat16*)p;
    cudaGetSymbolAddress(&p, g_yh);   __nv_bfloat16* yh  = (__nv_bfloat16*)p;
    cudaGetSymbolAddress(&p, g_yl);   __nv_bfloat16* yl  = (__nv_bfloat16*)p;
    cudaGetSymbolAddress(&p, g_fkh);  __nv_bfloat16* fkh = (__nv_bfloat16*)p;
    cudaGetSymbolAddress(&p, g_fkl);  __nv_bfloat16* fkl = (__nv_bfloat16*)p;
    cudaGetSymbolAddress(&p, g_wkh);  __nv_bfloat16* wkh = (__nv_bfloat16*)p;
    cudaGetSymbolAddress(&p, g_wkl);  __nv_bfloat16* wkl = (__nv_bfloat16*)p;
    cudaGetSymbolAddress(&p, g_wvh);  __nv_bfloat16* wvh = (__nv_bfloat16*)p;
    cudaGetSymbolAddress(&p, g_wvl);  __nv_bfloat16* wvl = (__nv_bfloat16*)p;
    cudaGetSymbolAddress(&p, g_wrh);  __nv_bfloat16* wrh = (__nv_bfloat16*)p;
    cudaGetSymbolAddress(&p, g_wrl);  __nv_bfloat16* wrl = (__nv_bfloat16*)p;
    cudaGetSymbolAddress(&p, g_woh);  __nv_bfloat16* woh = (__nv_bfloat16*)p;
    cudaGetSymbolAddress(&p, g_wol);  __nv_bfloat16* wol = (__nv_bfloat16*)p;
    cudaGetSymbolAddress(&p, g_fwkh); __nv_bfloat16* fwkh = (__nv_bfloat16*)p;
    cudaGetSymbolAddress(&p, g_fwkl); __nv_bfloat16* fwkl = (__nv_bfloat16*)p;
    cudaGetSymbolAddress(&p, g_fwrh); __nv_bfloat16* fwrh = (__nv_bfloat16*)p;
    cudaGetSymbolAddress(&p, g_fwrl); __nv_bfloat16* fwrl = (__nv_bfloat16*)p;
    cudaGetSymbolAddress(&p, g_fwvh); __nv_bfloat16* fwvh = (__nv_bfloat16*)p;
    cudaGetSymbolAddress(&p, g_fwvl); __nv_bfloat16* fwvl = (__nv_bfloat16*)p;

    cudaFuncSetAttribute(gemm_kvr, cudaFuncAttributeMaxDynamicSharedMemorySize, SMEM_SZ);
    cudaFuncSetAttribute(gemm_ffnpre, cudaFuncAttributeMaxDynamicSharedMemorySize, SMEM_SZ);
    cudaFuncSetAttribute(gemm_acc<3>, cudaFuncAttributeMaxDynamicSharedMemorySize, SMEM_SZ);
    cudaFuncSetAttribute(gemm_acc<4>, cudaFuncAttributeMaxDynamicSharedMemorySize, SMEM_SZ);

    // ---- weight splits (once per launch) ----
    const int nW  = NL * AD * HD;
    const int nWI = NL * FI * HD;
    split_kernel<<<nW / 1024, 256>>>(wk, wkh, wkl, nW / 4);
    split_kernel<<<nW / 1024, 256>>>(wv, wvh, wvl, nW / 4);
    split_kernel<<<nW / 1024, 256>>>(wr, wrh, wrl, nW / 4);
    split_kernel<<<nW / 1024, 256>>>(wo, woh, wol, nW / 4);
    split_kernel<<<nWI / 1024, 256>>>(fwk, fwkh, fwkl, nWI / 4);
    split_kernel<<<nW / 1024, 256>>>(fwr, fwrh, fwrl, nW / 4);
    split_kernel<<<nWI / 1024, 256>>>(fwv, fwvh, fwvl, nWI / 4);

    const dim3 gKVR(HD / BN, NTOK / BM, 3);          // (8, 64, 3)
    const dim3 gH(HD / BN, NTOK / BM);               // (8, 64)
    const dim3 gFFN(FI / BN + HD / BN, NTOK / BM);   // (40, 64)

    embed_ln_kernel<<<NTOK, 256>>>(ids, emb, prew, preb, h);

    for (int i = 0; i < NL; i++) {
        const size_t oW  = (size_t)i * AD * HD;
        const size_t oWI = (size_t)i * FI * HD;
        // ---- attention / time mix ----
        ln_mix3_kernel<<<NTOK, 256>>>(h, ln1w + i * HD, ln1b + i * HD,
                                      mxk + i * HD, mxv + i * HD, mxr + i * HD,
                                      xkh, xkl, xvh, xvl, xrh, xrl);
        gemm_kvr<<<gKVR, 256, SMEM_SZ>>>(xkh, xkl, xvh, xvl, xrh, xrl,
                                         wkh + oW, wkl + oW, wvh + oW, wvl + oW,
                                         wrh + oW, wrl + oW, kb, vb, rb);
        wkv_kernel<<<NBB * AD / 256, 256>>>(tfir + i * AD, tdec + i * AD,
                                            kb, vb, rb, yh, yl);
        gemm_acc<3><<<gH, 256, SMEM_SZ>>>(yh, yl, woh + oW, wol + oW,
                                          h, nullptr, HD, AD);
        // ---- ffn / channel mix ----
        ln_mix2_kernel<<<NTOK, 256>>>(h, ln2w + i * HD, ln2b + i * HD,
                                      fmk + i * HD, fmr + i * HD,
                                      xkh, xkl, xrh, xrl);
        gemm_ffnpre<<<gFFN, 256, SMEM_SZ>>>(xkh, xkl, xrh, xrl,
                                            fwkh + oWI, fwkl + oWI,
                                            fwrh + oW, fwrl + oW,
                                            fkh, fkl, rb);
        gemm_acc<4><<<gH, 256, SMEM_SZ>>>(fkh, fkl, fwvh + oWI, fwvl + oWI,
                                          h, rb, HD, FI);
    }

    ln_kernel<<<NTOK, 256>>>(h, postw, postb, out);
}

// round 14
// speedup vs baseline: 1.2053x; 1.0030x over previous
#include <cuda_runtime.h>
#include <cuda_bf16.h>
#include <cstdint>

// ---------------- problem constants ----------------
#define NL    6
#define HD    1024
#define AD    1024
#define FI    4096
#define NBB   4
#define TSEQ  2048
#define NTOK  (NBB * TSEQ)     // 8192 tokens

// ---------------- GEMM tile constants (128x128, 2 CTAs/SM) ----------------
#define BM 128
#define BN 128
#define BK 64                  // bf16 elems per K tile (128B rows = SW128 atom)
#define STAGES 3
#define STAGE_A 16384
#define STAGE_B 16384
#define STAGE_BYTES (STAGE_A + STAGE_B)      // 32768
#define SMEM_SZ (STAGES * STAGE_BYTES)       // 98304 -> 2 CTAs/SM

#define SWZ(o) ((o) ^ ((((uint32_t)(o)) >> 3) & 0x70))

// ---------------- persistent scratch ----------------
__device__ __align__(16) float g_h[NTOK * HD];
__device__ __align__(16) float g_k[NTOK * AD];
__device__ __align__(16) float g_v[NTOK * AD];
__device__ __align__(16) float g_r[NTOK * AD];
__device__ __align__(16) __nv_bfloat16 g_xkh[NTOK * HD], g_xkl[NTOK * HD];
__device__ __align__(16) __nv_bfloat16 g_xvh[NTOK * HD], g_xvl[NTOK * HD];
__device__ __align__(16) __nv_bfloat16 g_xrh[NTOK * HD], g_xrl[NTOK * HD];
__device__ __align__(16) __nv_bfloat16 g_yh[NTOK * AD], g_yl[NTOK * AD];
__device__ __align__(16) __nv_bfloat16 g_fkh[NTOK * FI], g_fkl[NTOK * FI];
// weight hi/lo
__device__ __align__(16) __nv_bfloat16 g_wkh[NL * AD * HD], g_wkl[NL * AD * HD];
__device__ __align__(16) __nv_bfloat16 g_wvh[NL * AD * HD], g_wvl[NL * AD * HD];
__device__ __align__(16) __nv_bfloat16 g_wrh[NL * AD * HD], g_wrl[NL * AD * HD];
__device__ __align__(16) __nv_bfloat16 g_woh[NL * HD * AD], g_wol[NL * HD * AD];
__device__ __align__(16) __nv_bfloat16 g_fwkh[NL * FI * HD], g_fwkl[NL * FI * HD];
__device__ __align__(16) __nv_bfloat16 g_fwrh[NL * HD * HD], g_fwrl[NL * HD * HD];
__device__ __align__(16) __nv_bfloat16 g_fwvh[NL * HD * FI], g_fwvl[NL * HD * FI];

// ---------------- PTX helpers (portable sm_80+ features only) ----------------
__device__ __forceinline__ uint32_t smem_u32(const void* p) {
    uint32_t a;
    asm("{ .reg .u64 t; cvta.to.shared.u64 t, %1; cvt.u32.u64 %0, t; }"
        : "=r"(a) : "l"(p));
    return a;
}

#define CPASYNC16(saddr, gptr)                                                \
    asm volatile("cp.async.cg.shared.global [%0], [%1], 16;"                  \
                 :: "r"(saddr), "l"(gptr))
#define CPCOMMIT() asm volatile("cp.async.commit_group;" ::: "memory")
#define CPWAIT1()  asm volatile("cp.async.wait_group 1;" ::: "memory")

#define LDSM4(r0, r1, r2, r3, addr)                                           \
    asm volatile("ldmatrix.sync.aligned.m8n8.x4.shared.b16 {%0,%1,%2,%3}, [%4];" \
                 : "=r"(r0), "=r"(r1), "=r"(r2), "=r"(r3) : "r"(addr))

#define MMA16816(d, a, b)                                                     \
    asm volatile("mma.sync.aligned.m16n8k16.row.col.f32.bf16.bf16.f32 "       \
                 "{%0,%1,%2,%3}, {%4,%5,%6,%7}, {%8,%9}, {%0,%1,%2,%3};"      \
                 : "+f"((d)[0]), "+f"((d)[1]), "+f"((d)[2]), "+f"((d)[3])     \
                 : "r"((a)[0]), "r"((a)[1]), "r"((a)[2]), "r"((a)[3]),        \
                   "r"((b)[0]), "r"((b)[1]))

__device__ __forceinline__ void split_bf(float v, __nv_bfloat16& h, __nv_bfloat16& l) {
    h = __float2bfloat16(v);
    l = __float2bfloat16(v - __bfloat162float(h));
}

// ================= shared GEMM mainloop =================
// acc[n_tok 128][m_feat 128] = sum over 3 hi/lo segments of X[n,k]*W[m,k]
// Inner k-slice is software-pipelined: B fragments first, A fragments loaded
// one mf ahead of their MMAs so LDSM latency hides under tensor work.
__device__ __forceinline__ void gemm_mainloop(
    const __nv_bfloat16* __restrict__ Ah, const __nv_bfloat16* __restrict__ Al,
    const __nv_bfloat16* __restrict__ Bh, const __nv_bfloat16* __restrict__ Bl,
    int K, int tokBase, int featBase, char* smem, float (&c)[4][4][4]) {
    const uint32_t sb = smem_u32(smem);
    const int tid  = threadIdx.x;
    const int lane = tid & 31;
    const int wid  = tid >> 5;
    const int wm   = wid >> 2;          // 0..1
    const int wn   = wid & 3;           // 0..3
    const int lrow  = lane & 15;
    const int lhalf = lane >> 4;
    const int ktiles = K >> 6;
    const int TT = 3 * ktiles;

    // Loads: 2 threads per row, 4 x 16B chunks each, for both A and B.
    const int ldrow = tid >> 1;          // 0..127
    const int ldcb  = (tid & 1) << 2;    // chunk base 0 or 4
    const size_t aoff = (size_t)(tokBase + ldrow) * K + ldcb * 8;
    const size_t boff = (size_t)(featBase + ldrow) * K + ldcb * 8;
    uint32_t smoff[4];
#pragma unroll
    for (int j = 0; j < 4; j++)
        smoff[j] = SWZ(ldrow * 128 + (ldcb + j) * 16);

    auto issue = [&](int tt) {
        const int seg  = tt / ktiles;
        const int koff = (tt - seg * ktiles) << 6;
        const __nv_bfloat16* Ap = ((seg == 1) ? Al : Ah) + aoff + koff;
        const __nv_bfloat16* Bp = ((seg == 2) ? Bl : Bh) + boff + koff;
        const uint32_t st = sb + (uint32_t)(tt % STAGES) * STAGE_BYTES;
#pragma unroll
        for (int j = 0; j < 4; j++) {
            CPASYNC16(st + smoff[j], (const void*)__cvta_generic_to_global(Ap + j * 8));
            CPASYNC16(st + STAGE_A + smoff[j], (const void*)__cvta_generic_to_global(Bp + j * 8));
        }
    };

#pragma unroll
    for (int i = 0; i < 4; i++)
#pragma unroll
        for (int j = 0; j < 4; j++)
#pragma unroll
            for (int q = 0; q < 4; q++) c[i][j][q] = 0.f;

    issue(0); CPCOMMIT();
    issue(1); CPCOMMIT();

    // Per-warp base addresses (row term only; kcol XORed per slice).
    const uint32_t arow0 = (uint32_t)(wm * 64 + lrow) * 128;
    const uint32_t brow0 = (uint32_t)(wn * 32 + lrow) * 128;

    for (int tt = 0; tt < TT; tt++) {
        CPWAIT1();
        __syncthreads();
        if (tt + 2 < TT) issue(tt + 2);
        CPCOMMIT();

        const uint32_t Ab = sb + (uint32_t)(tt % STAGES) * STAGE_BYTES;
        const uint32_t Bb = Ab + STAGE_A;
#pragma unroll
        for (int ks = 0; ks < 4; ks++) {
            const uint32_t kcol = (uint32_t)(ks * 2 + lhalf) * 16;
            // ---- B fragments for this k16 slice (2 x LDSM4 = 4 n8 frags)
            uint32_t b[4][2];
#pragma unroll
            for (int g = 0; g < 2; g++) {
                uint32_t r0, r1, r2, r3;
                uint32_t bd = Bb + SWZ(brow0 + (uint32_t)(g * 16 * 128) + kcol);
                LDSM4(r0, r1, r2, r3, bd);
                b[2 * g][0] = r0;     b[2 * g][1] = r2;
                b[2 * g + 1][0] = r1; b[2 * g + 1][1] = r3;
            }
            // ---- rolling A fragments: load mf+1 while doing MMAs of mf
            uint32_t a[2][4];
            {
                uint32_t ad = Ab + SWZ(arow0 + kcol);
                LDSM4(a[0][0], a[0][1], a[0][2], a[0][3], ad);
            }
#pragma unroll
            for (int mf = 0; mf < 4; mf++) {
                if (mf < 3) {
                    uint32_t ad = Ab + SWZ(arow0 + (uint32_t)((mf + 1) * 16 * 128) + kcol);
                    LDSM4(a[(mf + 1) & 1][0], a[(mf + 1) & 1][1],
                          a[(mf + 1) & 1][2], a[(mf + 1) & 1][3], ad);
                }
#pragma unroll
                for (int nf = 0; nf < 4; nf++)
                    MMA16816(c[mf][nf], a[mf & 1], b[nf]);
            }
        }
    }
}

// Epilogue tile walk helper macro (variadic: body may contain commas).
// Body sees: r (token row), col (feature col), vx, vy (acc pair), idx.
#define EPI_WALK(Mfeat, ...)                                                  \
    do {                                                                      \
        const int lane = threadIdx.x & 31;                                    \
        const int wid  = threadIdx.x >> 5;                                    \
        const int rbase = tokBase + (wid >> 2) * 64 + (lane >> 2);            \
        const int cbase = featBase + (wid & 3) * 32 + (lane & 3) * 2;         \
        _Pragma("unroll")                                                     \
        for (int mf = 0; mf < 4; mf++) {                                      \
            _Pragma("unroll")                                                 \
            for (int nf = 0; nf < 4; nf++) {                                  \
                const int col = cbase + nf * 8;                               \
                _Pragma("unroll")                                             \
                for (int half = 0; half < 2; half++) {                        \
                    const int r = rbase + mf * 16 + half * 8;                 \
                    float vx = c[mf][nf][half * 2 + 0];                       \
                    float vy = c[mf][nf][half * 2 + 1];                       \
                    const size_t idx = (size_t)r * (Mfeat) + col;             \
                    __VA_ARGS__                                               \
                }                                                             \
            }                                                                 \
        }                                                                     \
    } while (0)

// ---- k/v/r projections fused via blockIdx.z (z=2 -> sigmoid) ----
__global__ __launch_bounds__(256, 2)
void gemm_kvr(const __nv_bfloat16* __restrict__ xkh, const __nv_bfloat16* __restrict__ xkl,
              const __nv_bfloat16* __restrict__ xvh, const __nv_bfloat16* __restrict__ xvl,
              const __nv_bfloat16* __restrict__ xrh, const __nv_bfloat16* __restrict__ xrl,
              const __nv_bfloat16* __restrict__ wkh, const __nv_bfloat16* __restrict__ wkl,
              const __nv_bfloat16* __restrict__ wvh, const __nv_bfloat16* __restrict__ wvl,
              const __nv_bfloat16* __restrict__ wrh, const __nv_bfloat16* __restrict__ wrl,
              float* __restrict__ kb, float* __restrict__ vb, float* __restrict__ rb) {
    extern __shared__ char smem[];
    const int z = blockIdx.z;
    const int tokBase  = blockIdx.y << 7;
    const int featBase = blockIdx.x << 7;
    const __nv_bfloat16 *Ah, *Al, *Bh, *Bl;
    float* C;
    if (z == 0)      { Ah = xkh; Al = xkl; Bh = wkh; Bl = wkl; C = kb; }
    else if (z == 1) { Ah = xvh; Al = xvl; Bh = wvh; Bl = wvl; C = vb; }
    else             { Ah = xrh; Al = xrl; Bh = wrh; Bl = wrl; C = rb; }
    float c[4][4][4];
    gemm_mainloop(Ah, Al, Bh, Bl, HD, tokBase, featBase, smem, c);
    if (z == 2) {
        EPI_WALK(AD, {
            vx = 1.f / (1.f + __expf(-vx));
            vy = 1.f / (1.f + __expf(-vy));
            *(float2*)(C + idx) = make_float2(vx, vy);
        });
    } else {
        EPI_WALK(AD, { *(float2*)(C + idx) = make_float2(vx, vy); });
    }
}

// ---- FFN fwk (relu^2 -> bf16 split) + fwr (sigmoid) fused via blockIdx.x ----
__global__ __launch_bounds__(256, 2)
void gemm_ffnpre(const __nv_bfloat16* __restrict__ xkh, const __nv_bfloat16* __restrict__ xkl,
                 const __nv_bfloat16* __restrict__ xrh, const __nv_bfloat16* __restrict__ xrl,
                 const __nv_bfloat16* __restrict__ fwkh, const __nv_bfloat16* __restrict__ fwkl,
                 const __nv_bfloat16* __restrict__ fwrh, const __nv_bfloat16* __restrict__ fwrl,
                 __nv_bfloat16* __restrict__ fkh, __nv_bfloat16* __restrict__ fkl,
                 float* __restrict__ rb) {
    extern __shared__ char smem[];
    const int bx = blockIdx.x;
    const int tokBase = blockIdx.y << 7;
    const bool isK = (bx < (FI / BN));
    const int featBase = (isK ? bx : bx - FI / BN) << 7;
    float c[4][4][4];
    if (isK) {
        gemm_mainloop(xkh, xkl, fwkh, fwkl, HD, tokBase, featBase, smem, c);
        EPI_WALK(FI, {
            vx = fmaxf(vx, 0.f); vx = vx * vx;
            vy = fmaxf(vy, 0.f); vy = vy * vy;
            __nv_bfloat16 hx, lx, hy, ly;
            split_bf(vx, hx, lx);
            split_bf(vy, hy, ly);
            *(__nv_bfloat162*)(fkh + idx) = __nv_bfloat162(hx, hy);
            *(__nv_bfloat162*)(fkl + idx) = __nv_bfloat162(lx, ly);
        });
    } else {
        gemm_mainloop(xrh, xrl, fwrh, fwrl, HD, tokBase, featBase, smem, c);
        EPI_WALK(HD, {
            vx = 1.f / (1.f + __expf(-vx));
            vy = 1.f / (1.f + __expf(-vy));
            *(float2*)(rb + idx) = make_float2(vx, vy);
        });
    }
}

// ---- generic accumulate GEMMs: EPI 3 (C+=v), EPI 4 (C+=aux*v) ----
template <int EPI>
__global__ __launch_bounds__(256, 2)
void gemm_acc(const __nv_bfloat16* __restrict__ Ah, const __nv_bfloat16* __restrict__ Al,
              const __nv_bfloat16* __restrict__ Bh, const __nv_bfloat16* __restrict__ Bl,
              float* __restrict__ C, const float* __restrict__ aux, int Mfeat, int K) {
    extern __shared__ char smem[];
    const int tokBase  = blockIdx.y << 7;
    const int featBase = blockIdx.x << 7;
    float c[4][4][4];
    gemm_mainloop(Ah, Al, Bh, Bl, K, tokBase, featBase, smem, c);
    if (EPI == 3) {
        EPI_WALK(Mfeat, {
            float2 cur = *(float2*)(C + idx);
            cur.x += vx; cur.y += vy;
            *(float2*)(C + idx) = cur;
        });
    } else {
        EPI_WALK(Mfeat, {
            float2 cur = *(float2*)(C + idx);
            float2 a2 = *(const float2*)(aux + idx);
            cur.x = fmaf(a2.x, vx, cur.x);
            cur.y = fmaf(a2.y, vy, cur.y);
            *(float2*)(C + idx) = cur;
        });
    }
}

// ---------------- block reduction / layernorm ----------------
__device__ __forceinline__ float blkSum(float v) {
#pragma unroll
    for (int o = 16; o; o >>= 1) v += __shfl_xor_sync(0xffffffffu, v, o);
    __shared__ float sh[8];
    int w = threadIdx.x >> 5, l = threadIdx.x & 31;
    __syncthreads();
    if (l == 0) sh[w] = v;
    __syncthreads();
    float s = 0.f;
#pragma unroll
    for (int i = 0; i < 8; i++) s += sh[i];
    return s;
}

__device__ __forceinline__ float4 ln_reg(const float* __restrict__ row,
                                         const float* __restrict__ w,
                                         const float* __restrict__ b) {
    int t = threadIdx.x;
    float4 v = ((const float4*)row)[t];
    float s = blkSum(v.x + v.y + v.z + v.w);
    float mu = s * (1.f / HD);
    float dx = v.x - mu, dy = v.y - mu, dz = v.z - mu, dw = v.w - mu;
    float sq = blkSum(dx * dx + dy * dy + dz * dz + dw * dw);
    float rstd = rsqrtf(sq * (1.f / HD) + 1e-5f);
    float4 wv = ((const float4*)w)[t];
    float4 bv = ((const float4*)b)[t];
    float4 o;
    o.x = dx * rstd * wv.x + bv.x;
    o.y = dy * rstd * wv.y + bv.y;
    o.z = dz * rstd * wv.z + bv.z;
    o.w = dw * rstd * wv.w + bv.w;
    return o;
}

__global__ void ln_kernel(const float* __restrict__ in, const float* __restrict__ w,
                          const float* __restrict__ b, float* __restrict__ out) {
    size_t n = blockIdx.x;
    float4 o = ln_reg(in + n * HD, w, b);
    ((float4*)(out + n * HD))[threadIdx.x] = o;
}

__global__ void embed_ln_kernel(const int* __restrict__ ids, const float* __restrict__ emb,
                                const float* __restrict__ w, const float* __restrict__ b,
                                float* __restrict__ out) {
    size_t n = blockIdx.x;
    size_t idx = (size_t)ids[n];
    float4 o = ln_reg(emb + idx * HD, w, b);
    ((float4*)(out + n * HD))[threadIdx.x] = o;
}

// ---------------- fused LN + token-shift mix (emit bf16 hi/lo) ----------------
__device__ __forceinline__ void mix_store(float mc, float xc, float xp,
                                          __nv_bfloat16& hh, __nv_bfloat16& ll) {
    float v = mc * xc + (1.f - mc) * xp;
    split_bf(v, hh, ll);
}

__device__ __forceinline__ void store_pair4(__nv_bfloat16* __restrict__ H,
                                            __nv_bfloat16* __restrict__ L, size_t i,
                                            const float4& m4, const float4& xc,
                                            const float4& xp) {
    __nv_bfloat16 h0, l0, h1, l1, h2, l2, h3, l3;
    mix_store(m4.x, xc.x, xp.x, h0, l0);
    mix_store(m4.y, xc.y, xp.y, h1, l1);
    mix_store(m4.z, xc.z, xp.z, h2, l2);
    mix_store(m4.w, xc.w, xp.w, h3, l3);
    ((__nv_bfloat162*)(H + i))[0] = __nv_bfloat162(h0, h1);
    ((__nv_bfloat162*)(H + i))[1] = __nv_bfloat162(h2, h3);
    ((__nv_bfloat162*)(L + i))[0] = __nv_bfloat162(l0, l1);
    ((__nv_bfloat162*)(L + i))[1] = __nv_bfloat162(l2, l3);
}

__global__ void ln_mix3_kernel(const float* __restrict__ h,
                               const float* __restrict__ w, const float* __restrict__ b,
                               const float* __restrict__ mk, const float* __restrict__ mv,
                               const float* __restrict__ mr,
                               __nv_bfloat16* __restrict__ xkh, __nv_bfloat16* __restrict__ xkl,
                               __nv_bfloat16* __restrict__ xvh, __nv_bfloat16* __restrict__ xvl,
                               __nv_bfloat16* __restrict__ xrh, __nv_bfloat16* __restrict__ xrl) {
    size_t n = blockIdx.x;
    int t = (int)(n & (TSEQ - 1));
    float4 xc = ln_reg(h + n * HD, w, b);
    float4 xp = make_float4(0.f, 0.f, 0.f, 0.f);
    if (t) xp = ln_reg(h + (n - 1) * HD, w, b);
    size_t i = n * HD + (size_t)threadIdx.x * 4;
    store_pair4(xkh, xkl, i, ((const float4*)mk)[threadIdx.x], xc, xp);
    store_pair4(xvh, xvl, i, ((const float4*)mv)[threadIdx.x], xc, xp);
    store_pair4(xrh, xrl, i, ((const float4*)mr)[threadIdx.x], xc, xp);
}

__global__ void ln_mix2_kernel(const float* __restrict__ h,
                               const float* __restrict__ w, const float* __restrict__ b,
                               const float* __restrict__ mk, const float* __restrict__ mr,
                               __nv_bfloat16* __restrict__ xkh, __nv_bfloat16* __restrict__ xkl,
                               __nv_bfloat16* __restrict__ xrh, __nv_bfloat16* __restrict__ xrl) {
    size_t n = blockIdx.x;
    int t = (int)(n & (TSEQ - 1));
    float4 xc = ln_reg(h + n * HD, w, b);
    float4 xp = make_float4(0.f, 0.f, 0.f, 0.f);
    if (t) xp = ln_reg(h + (n - 1) * HD, w, b);
    size_t i = n * HD + (size_t)threadIdx.x * 4;
    store_pair4(xkh, xkl, i, ((const float4*)mk)[threadIdx.x], xc, xp);
    store_pair4(xrh, xrl, i, ((const float4*)mr)[threadIdx.x], xc, xp);
}

// ---------------- weight split fp32 -> bf16 hi/lo ----------------
__global__ void split_kernel(const float* __restrict__ src,
                             __nv_bfloat16* __restrict__ h, __nv_bfloat16* __restrict__ l,
                             int n4) {
    int i = (blockIdx.x * 256 + threadIdx.x);
    if (i >= n4) return;
    float4 v = ((const float4*)src)[i];
    __nv_bfloat16 h0, h1, h2, h3, l0, l1, l2, l3;
    split_bf(v.x, h0, l0); split_bf(v.y, h1, l1);
    split_bf(v.z, h2, l2); split_bf(v.w, h3, l3);
    __nv_bfloat162* Hp = (__nv_bfloat162*)(h + (size_t)i * 4);
    __nv_bfloat162* Lp = (__nv_bfloat162*)(l + (size_t)i * 4);
    Hp[0] = __nv_bfloat162(h0, h1); Hp[1] = __nv_bfloat162(h2, h3);
    Lp[0] = __nv_bfloat162(l0, l1); Lp[1] = __nv_bfloat162(l2, l3);
}

// ---------------- WKV scan (emits y hi/lo bf16) ----------------
__global__ void wkv_kernel(const float* __restrict__ tf, const float* __restrict__ td,
                           const float* __restrict__ k, const float* __restrict__ v,
                           const float* __restrict__ r,
                           __nv_bfloat16* __restrict__ yh, __nv_bfloat16* __restrict__ yl) {
    int laneid = blockIdx.x * 256 + threadIdx.x;
    int b = laneid >> 10;
    int a = laneid & (AD - 1);
    float u = tf[a];
    float w = -__expf(td[a]);
    float aa = 0.f, bb = 0.f, pp = -1e38f;
    size_t base = ((size_t)b * TSEQ) * AD + a;
    float kt = k[base], vt = v[base], rt = r[base];
    for (int t = 0; t < TSEQ; t++) {
        size_t off = base + (size_t)t * AD;
        float kn = 0.f, vn = 0.f, rn = 0.f;
        if (t + 1 < TSEQ) { kn = k[off + AD]; vn = v[off + AD]; rn = r[off + AD]; }
        float uk = u + kt;
        float q = fmaxf(pp, uk);
        float e1 = __expf(uk - q);
        float e2 = __expf(pp - q);
        float num = fmaf(aa, e2, e1 * vt);
        float den = fmaf(bb, e2, e1);
        float o = rt * (num / den);
        __nv_bfloat16 hh, ll;
        split_bf(o, hh, ll);
        yh[off] = hh; yl[off] = ll;
        float pw = pp + w;
        float q2 = fmaxf(pw, kt);
        float s1 = __expf(pw - q2);
        float s2 = __expf(kt - q2);
        aa = fmaf(s1, aa, s2 * vt);
        bb = fmaf(s1, bb, s2);
        pp = q2;
        kt = kn; vt = vn; rt = rn;
    }
}

// ---------------- orchestration ----------------
extern "C" void kernel_launch(void* const* d_in, const int* in_sizes, int n_in,
                              void* d_out, int out_size) {
    const int*   ids   = (const int*)d_in[0];
    const float* emb   = (const float*)d_in[1];
    const float* prew  = (const float*)d_in[2];
    const float* preb  = (const float*)d_in[3];
    const float* postw = (const float*)d_in[4];
    const float* postb = (const float*)d_in[5];
    const float* ln1w  = (const float*)d_in[6];
    const float* ln1b  = (const float*)d_in[7];
    const float* ln2w  = (const float*)d_in[8];
    const float* ln2b  = (const float*)d_in[9];
    const float* mxk   = (const float*)d_in[10];
    const float* mxv   = (const float*)d_in[11];
    const float* mxr   = (const float*)d_in[12];
    const float* wk    = (const float*)d_in[13];
    const float* wv    = (const float*)d_in[14];
    const float* wr    = (const float*)d_in[15];
    const float* wo    = (const float*)d_in[16];
    const float* tdec  = (const float*)d_in[17];
    const float* tfir  = (const float*)d_in[18];
    const float* fmk   = (const float*)d_in[19];
    const float* fmr   = (const float*)d_in[20];
    const float* fwk   = (const float*)d_in[21];
    const float* fwr   = (const float*)d_in[22];
    const float* fwv   = (const float*)d_in[23];
    float* out = (float*)d_out;

    void* p;
    cudaGetSymbolAddress(&p, g_h);    float* h  = (float*)p;
    cudaGetSymbolAddress(&p, g_k);    float* kb = (float*)p;
    cudaGetSymbolAddress(&p, g_v);    float* vb = (float*)p;
    cudaGetSymbolAddress(&p, g_r);    float* rb = (float*)p;
    cudaGetSymbolAddress(&p, g_xkh);  __nv_bfloat16* xkh = (__nv_bfloat16*)p;
    cudaGetSymbolAddress(&p, g_xkl);  __nv_bfloat16* xkl = (__nv_bfloat16*)p;
    cudaGetSymbolAddress(&p, g_xvh);  __nv_bfloat16* xvh = (__nv_bfloat16*)p;
    cudaGetSymbolAddress(&p, g_xvl);  __nv_bfloat16* xvl = (__nv_bfloat16*)p;
    cudaGetSymbolAddress(&p, g_xrh);  __nv_bfloat16* xrh = (__nv_bfloat16*)p;
    cudaGetSymbolAddress(&p, g_xrl);  __nv_bfloat16* xrl = (__nv_bfloat16*)p;
    cudaGetSymbolAddress(&p, g_yh);   __nv_bfloat16* yh  = (__nv_bfloat16*)p;
    cudaGetSymbolAddress(&p, g_yl);   __nv_bfloat16* yl  = (__nv_bfloat16*)p;
    cudaGetSymbolAddress(&p, g_fkh);  __nv_bfloat16* fkh = (__nv_bfloat16*)p;
    cudaGetSymbolAddress(&p, g_fkl);  __nv_bfloat16* fkl = (__nv_bfloat16*)p;
    cudaGetSymbolAddress(&p, g_wkh);  __nv_bfloat16* wkh = (__nv_bfloat16*)p;
    cudaGetSymbolAddress(&p, g_wkl);  __nv_bfloat16* wkl = (__nv_bfloat16*)p;
    cudaGetSymbolAddress(&p, g_wvh);  __nv_bfloat16* wvh = (__nv_bfloat16*)p;
    cudaGetSymbolAddress(&p, g_wvl);  __nv_bfloat16* wvl = (__nv_bfloat16*)p;
    cudaGetSymbolAddress(&p, g_wrh);  __nv_bfloat16* wrh = (__nv_bfloat16*)p;
    cudaGetSymbolAddress(&p, g_wrl);  __nv_bfloat16* wrl = (__nv_bfloat16*)p;
    cudaGetSymbolAddress(&p, g_woh);  __nv_bfloat16* woh = (__nv_bfloat16*)p;
    cudaGetSymbolAddress(&p, g_wol);  __nv_bfloat16* wol = (__nv_bfloat16*)p;
    cudaGetSymbolAddress(&p, g_fwkh); __nv_bfloat16* fwkh = (__nv_bfloat16*)p;
    cudaGetSymbolAddress(&p, g_fwkl); __nv_bfloat16* fwkl = (__nv_bfloat16*)p;
    cudaGetSymbolAddress(&p, g_fwrh); __nv_bfloat16* fwrh = (__nv_bfloat16*)p;
    cudaGetSymbolAddress(&p, g_fwrl); __nv_bfloat16* fwrl = (__nv_bfloat16*)p;
    cudaGetSymbolAddress(&p, g_fwvh); __nv_bfloat16* fwvh = (__nv_bfloat16*)p;
    cudaGetSymbolAddress(&p, g_fwvl); __nv_bfloat16* fwvl = (__nv_bfloat16*)p;

    cudaFuncSetAttribute(gemm_kvr, cudaFuncAttributeMaxDynamicSharedMemorySize, SMEM_SZ);
    cudaFuncSetAttribute(gemm_ffnpre, cudaFuncAttributeMaxDynamicSharedMemorySize, SMEM_SZ);
    cudaFuncSetAttribute(gemm_acc<3>, cudaFuncAttributeMaxDynamicSharedMemorySize, SMEM_SZ);
    cudaFuncSetAttribute(gemm_acc<4>, cudaFuncAttributeMaxDynamicSharedMemorySize, SMEM_SZ);

    // ---- weight splits (once per launch) ----
    const int nW  = NL * AD * HD;
    const int nWI = NL * FI * HD;
    split_kernel<<<nW / 1024, 256>>>(wk, wkh, wkl, nW / 4);
    split_kernel<<<nW / 1024, 256>>>(wv, wvh, wvl, nW / 4);
    split_kernel<<<nW / 1024, 256>>>(wr, wrh, wrl, nW / 4);
    split_kernel<<<nW / 1024, 256>>>(wo, woh, wol, nW / 4);
    split_kernel<<<nWI / 1024, 256>>>(fwk, fwkh, fwkl, nWI / 4);
    split_kernel<<<nW / 1024, 256>>>(fwr, fwrh, fwrl, nW / 4);
    split_kernel<<<nWI / 1024, 256>>>(fwv, fwvh, fwvl, nWI / 4);

    const dim3 gKVR(HD / BN, NTOK / BM, 3);          // (8, 64, 3)
    const dim3 gH(HD / BN, NTOK / BM);               // (8, 64)
    const dim3 gFFN(FI / BN + HD / BN, NTOK / BM);   // (40, 64)

    embed_ln_kernel<<<NTOK, 256>>>(ids, emb, prew, preb, h);

    for (int i = 0; i < NL; i++) {
        const size_t oW  = (size_t)i * AD * HD;
        const size_t oWI = (size_t)i * FI * HD;
        // ---- attention / time mix ----
        ln_mix3_kernel<<<NTOK, 256>>>(h, ln1w + i * HD, ln1b + i * HD,
                                      mxk + i * HD, mxv + i * HD, mxr + i * HD,
                                      xkh, xkl, xvh, xvl, xrh, xrl);
        gemm_kvr<<<gKVR, 256, SMEM_SZ>>>(xkh, xkl, xvh, xvl, xrh, xrl,
                                         wkh + oW, wkl + oW, wvh + oW, wvl + oW,
                                         wrh + oW, wrl + oW, kb, vb, rb);
        wkv_kernel<<<NBB * AD / 256, 256>>>(tfir + i * AD, tdec + i * AD,
                                            kb, vb, rb, yh, yl);
        gemm_acc<3><<<gH, 256, SMEM_SZ>>>(yh, yl, woh + oW, wol + oW,
                                          h, nullptr, HD, AD);
        // ---- ffn / channel mix ----
        ln_mix2_kernel<<<NTOK, 256>>>(h, ln2w + i * HD, ln2b + i * HD,
                                      fmk + i * HD, fmr + i * HD,
                                      xkh, xkl, xrh, xrl);
        gemm_ffnpre<<<gFFN, 256, SMEM_SZ>>>(xkh, xkl, xrh, xrl,
                                            fwkh + oWI, fwkl + oWI,
                                            fwrh + oW, fwrl + oW,
                                            fkh, fkl, rb);
        gemm_acc<4><<<gH, 256, SMEM_SZ>>>(fkh, fkl, fwvh + oWI, fwvl + oWI,
                                          h, rb, HD, FI);
    }

    ln_kernel<<<NTOK, 256>>>(h, postw, postb, out);
}

// round 17
// speedup vs baseline: 1.5846x; 1.3147x over previous
#include <cuda_runtime.h>
#include <cuda_fp16.h>
#include <cstdint>

// ---------------- problem constants ----------------
#define NL    6
#define HD    1024
#define AD    1024
#define FI    4096
#define NBB   4
#define TSEQ  2048
#define NTOK  (NBB * TSEQ)     // 8192 tokens

// ---------------- GEMM tile constants (128x128, 2 CTAs/SM) ----------------
#define BM 128
#define BN 128
#define BK 64                  // fp16 elems per K tile (128B rows = SW128 atom)
#define STAGES 3
#define STAGE_A 16384
#define STAGE_B 16384
#define STAGE_BYTES (STAGE_A + STAGE_B)      // 32768
#define SMEM_SZ (STAGES * STAGE_BYTES)       // 98304 -> 2 CTAs/SM

#define SWZ(o) ((o) ^ ((((uint32_t)(o)) >> 3) & 0x70))

// ---------------- persistent scratch ----------------
__device__ __align__(16) float g_h[NTOK * HD];
__device__ __align__(16) float g_k[NTOK * AD];
__device__ __align__(16) float g_v[NTOK * AD];
__device__ __align__(16) float g_r[NTOK * AD];
__device__ __align__(16) __half g_xkh[NTOK * HD], g_xkl[NTOK * HD];
__device__ __align__(16) __half g_xvh[NTOK * HD], g_xvl[NTOK * HD];
__device__ __align__(16) __half g_xrh[NTOK * HD], g_xrl[NTOK * HD];
__device__ __align__(16) __half g_yh[NTOK * AD], g_yl[NTOK * AD];
__device__ __align__(16) __half g_fkh[NTOK * FI], g_fkl[NTOK * FI];
// weights: hi-only fp16 (lo term dropped by the 2-segment scheme)
__device__ __align__(16) __half g_wkh[NL * AD * HD];
__device__ __align__(16) __half g_wvh[NL * AD * HD];
__device__ __align__(16) __half g_wrh[NL * AD * HD];
__device__ __align__(16) __half g_woh[NL * HD * AD];
__device__ __align__(16) __half g_fwkh[NL * FI * HD];
__device__ __align__(16) __half g_fwrh[NL * HD * HD];
__device__ __align__(16) __half g_fwvh[NL * HD * FI];

// ---------------- PTX helpers (portable sm_80+ features only) ----------------
__device__ __forceinline__ uint32_t smem_u32(const void* p) {
    uint32_t a;
    asm("{ .reg .u64 t; cvta.to.shared.u64 t, %1; cvt.u32.u64 %0, t; }"
        : "=r"(a) : "l"(p));
    return a;
}

#define CPASYNC16(saddr, gptr)                                                \
    asm volatile("cp.async.cg.shared.global [%0], [%1], 16;"                  \
                 :: "r"(saddr), "l"(gptr))
#define CPCOMMIT() asm volatile("cp.async.commit_group;" ::: "memory")
#define CPWAIT1()  asm volatile("cp.async.wait_group 1;" ::: "memory")

#define LDSM4(r0, r1, r2, r3, addr)                                           \
    asm volatile("ldmatrix.sync.aligned.m8n8.x4.shared.b16 {%0,%1,%2,%3}, [%4];" \
                 : "=r"(r0), "=r"(r1), "=r"(r2), "=r"(r3) : "r"(addr))

#define MMA16816(d, a, b)                                                     \
    asm volatile("mma.sync.aligned.m16n8k16.row.col.f32.f16.f16.f32 "         \
                 "{%0,%1,%2,%3}, {%4,%5,%6,%7}, {%8,%9}, {%0,%1,%2,%3};"      \
                 : "+f"((d)[0]), "+f"((d)[1]), "+f"((d)[2]), "+f"((d)[3])     \
                 : "r"((a)[0]), "r"((a)[1]), "r"((a)[2]), "r"((a)[3]),        \
                   "r"((b)[0]), "r"((b)[1]))

__device__ __forceinline__ void split_h(float v, __half& h, __half& l) {
    h = __float2half_rn(v);
    l = __float2half_rn(v - __half2float(h));
}

// ================= shared GEMM mainloop =================
// acc[n_tok 128][m_feat 128] = Ah*Bh + Al*Bh  (fp16 2-segment split;
// dropped Ah*Bl term ~2^-12 relative). Inner k-slice keeps R14's rolling-A
// pipeline; B pointer is identical for both segments (second pass L2-hits).
__device__ __forceinline__ void gemm_mainloop(
    const __half* __restrict__ Ah, const __half* __restrict__ Al,
    const __half* __restrict__ Bh,
    int K, int tokBase, int featBase, char* smem, float (&c)[4][4][4]) {
    const uint32_t sb = smem_u32(smem);
    const int tid  = threadIdx.x;
    const int lane = tid & 31;
    const int wid  = tid >> 5;
    const int wm   = wid >> 2;          // 0..1
    const int wn   = wid & 3;           // 0..3
    const int lrow  = lane & 15;
    const int lhalf = lane >> 4;
    const int ktiles = K >> 6;
    const int TT = 2 * ktiles;

    // Loads: 2 threads per row, 4 x 16B chunks each, for both A and B.
    const int ldrow = tid >> 1;          // 0..127
    const int ldcb  = (tid & 1) << 2;    // chunk base 0 or 4
    const size_t aoff = (size_t)(tokBase + ldrow) * K + ldcb * 8;
    const size_t boff = (size_t)(featBase + ldrow) * K + ldcb * 8;
    uint32_t smoff[4];
#pragma unroll
    for (int j = 0; j < 4; j++)
        smoff[j] = SWZ(ldrow * 128 + (ldcb + j) * 16);

    auto issue = [&](int tt) {
        const int seg  = (tt >= ktiles) ? 1 : 0;
        const int koff = (tt - seg * ktiles) << 6;
        const __half* Ap = (seg ? Al : Ah) + aoff + koff;
        const __half* Bp = Bh + boff + koff;
        const uint32_t st = sb + (uint32_t)(tt % STAGES) * STAGE_BYTES;
#pragma unroll
        for (int j = 0; j < 4; j++) {
            CPASYNC16(st + smoff[j], (const void*)__cvta_generic_to_global(Ap + j * 8));
            CPASYNC16(st + STAGE_A + smoff[j], (const void*)__cvta_generic_to_global(Bp + j * 8));
        }
    };

#pragma unroll
    for (int i = 0; i < 4; i++)
#pragma unroll
        for (int j = 0; j < 4; j++)
#pragma unroll
            for (int q = 0; q < 4; q++) c[i][j][q] = 0.f;

    issue(0); CPCOMMIT();
    issue(1); CPCOMMIT();

    // Per-warp base addresses (row term only; kcol XORed per slice).
    const uint32_t arow0 = (uint32_t)(wm * 64 + lrow) * 128;
    const uint32_t brow0 = (uint32_t)(wn * 32 + lrow) * 128;

    for (int tt = 0; tt < TT; tt++) {
        CPWAIT1();
        __syncthreads();
        if (tt + 2 < TT) issue(tt + 2);
        CPCOMMIT();

        const uint32_t Ab = sb + (uint32_t)(tt % STAGES) * STAGE_BYTES;
        const uint32_t Bb = Ab + STAGE_A;
#pragma unroll
        for (int ks = 0; ks < 4; ks++) {
            const uint32_t kcol = (uint32_t)(ks * 2 + lhalf) * 16;
            // ---- B fragments for this k16 slice (2 x LDSM4 = 4 n8 frags)
            uint32_t b[4][2];
#pragma unroll
            for (int g = 0; g < 2; g++) {
                uint32_t r0, r1, r2, r3;
                uint32_t bd = Bb + SWZ(brow0 + (uint32_t)(g * 16 * 128) + kcol);
                LDSM4(r0, r1, r2, r3, bd);
                b[2 * g][0] = r0;     b[2 * g][1] = r2;
                b[2 * g + 1][0] = r1; b[2 * g + 1][1] = r3;
            }
            // ---- rolling A fragments: load mf+1 while doing MMAs of mf
            uint32_t a[2][4];
            {
                uint32_t ad = Ab + SWZ(arow0 + kcol);
                LDSM4(a[0][0], a[0][1], a[0][2], a[0][3], ad);
            }
#pragma unroll
            for (int mf = 0; mf < 4; mf++) {
                if (mf < 3) {
                    uint32_t ad = Ab + SWZ(arow0 + (uint32_t)((mf + 1) * 16 * 128) + kcol);
                    LDSM4(a[(mf + 1) & 1][0], a[(mf + 1) & 1][1],
                          a[(mf + 1) & 1][2], a[(mf + 1) & 1][3], ad);
                }
#pragma unroll
                for (int nf = 0; nf < 4; nf++)
                    MMA16816(c[mf][nf], a[mf & 1], b[nf]);
            }
        }
    }
}

// Epilogue tile walk helper macro (variadic: body may contain commas).
// Body sees: r (token row), col (feature col), vx, vy (acc pair), idx.
#define EPI_WALK(Mfeat, ...)                                                  \
    do {                                                                      \
        const int lane = threadIdx.x & 31;                                    \
        const int wid  = threadIdx.x >> 5;                                    \
        const int rbase = tokBase + (wid >> 2) * 64 + (lane >> 2);            \
        const int cbase = featBase + (wid & 3) * 32 + (lane & 3) * 2;         \
        _Pragma("unroll")                                                     \
        for (int mf = 0; mf < 4; mf++) {                                      \
            _Pragma("unroll")                                                 \
            for (int nf = 0; nf < 4; nf++) {                                  \
                const int col = cbase + nf * 8;                               \
                _Pragma("unroll")                                             \
                for (int half = 0; half < 2; half++) {                        \
                    const int r = rbase + mf * 16 + half * 8;                 \
                    float vx = c[mf][nf][half * 2 + 0];                       \
                    float vy = c[mf][nf][half * 2 + 1];                       \
                    const size_t idx = (size_t)r * (Mfeat) + col;             \
                    __VA_ARGS__                                               \
                }                                                             \
            }                                                                 \
        }                                                                     \
    } while (0)

// ---- k/v/r projections fused via blockIdx.z (z=2 -> sigmoid) ----
__global__ __launch_bounds__(256, 2)
void gemm_kvr(const __half* __restrict__ xkh, const __half* __restrict__ xkl,
              const __half* __restrict__ xvh, const __half* __restrict__ xvl,
              const __half* __restrict__ xrh, const __half* __restrict__ xrl,
              const __half* __restrict__ wkh, const __half* __restrict__ wvh,
              const __half* __restrict__ wrh,
              float* __restrict__ kb, float* __restrict__ vb, float* __restrict__ rb) {
    extern __shared__ char smem[];
    const int z = blockIdx.z;
    const int tokBase  = blockIdx.y << 7;
    const int featBase = blockIdx.x << 7;
    const __half *Ah, *Al, *Bh;
    float* C;
    if (z == 0)      { Ah = xkh; Al = xkl; Bh = wkh; C = kb; }
    else if (z == 1) { Ah = xvh; Al = xvl; Bh = wvh; C = vb; }
    else             { Ah = xrh; Al = xrl; Bh = wrh; C = rb; }
    float c[4][4][4];
    gemm_mainloop(Ah, Al, Bh, HD, tokBase, featBase, smem, c);
    if (z == 2) {
        EPI_WALK(AD, {
            vx = 1.f / (1.f + __expf(-vx));
            vy = 1.f / (1.f + __expf(-vy));
            *(float2*)(C + idx) = make_float2(vx, vy);
        });
    } else {
        EPI_WALK(AD, { *(float2*)(C + idx) = make_float2(vx, vy); });
    }
}

// ---- FFN fwk (relu^2 -> fp16 split) + fwr (sigmoid) fused via blockIdx.x ----
__global__ __launch_bounds__(256, 2)
void gemm_ffnpre(const __half* __restrict__ xkh, const __half* __restrict__ xkl,
                 const __half* __restrict__ xrh, const __half* __restrict__ xrl,
                 const __half* __restrict__ fwkh, const __half* __restrict__ fwrh,
                 __half* __restrict__ fkh, __half* __restrict__ fkl,
                 float* __restrict__ rb) {
    extern __shared__ char smem[];
    const int bx = blockIdx.x;
    const int tokBase = blockIdx.y << 7;
    const bool isK = (bx < (FI / BN));
    const int featBase = (isK ? bx : bx - FI / BN) << 7;
    float c[4][4][4];
    if (isK) {
        gemm_mainloop(xkh, xkl, fwkh, HD, tokBase, featBase, smem, c);
        EPI_WALK(FI, {
            vx = fmaxf(vx, 0.f); vx = vx * vx;
            vy = fmaxf(vy, 0.f); vy = vy * vy;
            __half hx, lx, hy, ly;
            split_h(vx, hx, lx);
            split_h(vy, hy, ly);
            *(__half2*)(fkh + idx) = __halves2half2(hx, hy);
            *(__half2*)(fkl + idx) = __halves2half2(lx, ly);
        });
    } else {
        gemm_mainloop(xrh, xrl, fwrh, HD, tokBase, featBase, smem, c);
        EPI_WALK(HD, {
            vx = 1.f / (1.f + __expf(-vx));
            vy = 1.f / (1.f + __expf(-vy));
            *(float2*)(rb + idx) = make_float2(vx, vy);
        });
    }
}

// ---- generic accumulate GEMMs: EPI 3 (C+=v), EPI 4 (C+=aux*v) ----
template <int EPI>
__global__ __launch_bounds__(256, 2)
void gemm_acc(const __half* __restrict__ Ah, const __half* __restrict__ Al,
              const __half* __restrict__ Bh,
              float* __restrict__ C, const float* __restrict__ aux, int Mfeat, int K) {
    extern __shared__ char smem[];
    const int tokBase  = blockIdx.y << 7;
    const int featBase = blockIdx.x << 7;
    float c[4][4][4];
    gemm_mainloop(Ah, Al, Bh, K, tokBase, featBase, smem, c);
    if (EPI == 3) {
        EPI_WALK(Mfeat, {
            float2 cur = *(float2*)(C + idx);
            cur.x += vx; cur.y += vy;
            *(float2*)(C + idx) = cur;
        });
    } else {
        EPI_WALK(Mfeat, {
            float2 cur = *(float2*)(C + idx);
            float2 a2 = *(const float2*)(aux + idx);
            cur.x = fmaf(a2.x, vx, cur.x);
            cur.y = fmaf(a2.y, vy, cur.y);
            *(float2*)(C + idx) = cur;
        });
    }
}

// ---------------- block reduction / layernorm ----------------
__device__ __forceinline__ float blkSum(float v) {
#pragma unroll
    for (int o = 16; o; o >>= 1) v += __shfl_xor_sync(0xffffffffu, v, o);
    __shared__ float sh[8];
    int w = threadIdx.x >> 5, l = threadIdx.x & 31;
    __syncthreads();
    if (l == 0) sh[w] = v;
    __syncthreads();
    float s = 0.f;
#pragma unroll
    for (int i = 0; i < 8; i++) s += sh[i];
    return s;
}

__device__ __forceinline__ float4 ln_reg(const float* __restrict__ row,
                                         const float* __restrict__ w,
                                         const float* __restrict__ b) {
    int t = threadIdx.x;
    float4 v = ((const float4*)row)[t];
    float s = blkSum(v.x + v.y + v.z + v.w);
    float mu = s * (1.f / HD);
    float dx = v.x - mu, dy = v.y - mu, dz = v.z - mu, dw = v.w - mu;
    float sq = blkSum(dx * dx + dy * dy + dz * dz + dw * dw);
    float rstd = rsqrtf(sq * (1.f / HD) + 1e-5f);
    float4 wv = ((const float4*)w)[t];
    float4 bv = ((const float4*)b)[t];
    float4 o;
    o.x = dx * rstd * wv.x + bv.x;
    o.y = dy * rstd * wv.y + bv.y;
    o.z = dz * rstd * wv.z + bv.z;
    o.w = dw * rstd * wv.w + bv.w;
    return o;
}

__global__ void ln_kernel(const float* __restrict__ in, const float* __restrict__ w,
                          const float* __restrict__ b, float* __restrict__ out) {
    size_t n = blockIdx.x;
    float4 o = ln_reg(in + n * HD, w, b);
    ((float4*)(out + n * HD))[threadIdx.x] = o;
}

__global__ void embed_ln_kernel(const int* __restrict__ ids, const float* __restrict__ emb,
                                const float* __restrict__ w, const float* __restrict__ b,
                                float* __restrict__ out) {
    size_t n = blockIdx.x;
    size_t idx = (size_t)ids[n];
    float4 o = ln_reg(emb + idx * HD, w, b);
    ((float4*)(out + n * HD))[threadIdx.x] = o;
}

// ---------------- fused LN + token-shift mix (emit fp16 hi/lo) ----------------
__device__ __forceinline__ void mix_store(float mc, float xc, float xp,
                                          __half& hh, __half& ll) {
    float v = mc * xc + (1.f - mc) * xp;
    split_h(v, hh, ll);
}

__device__ __forceinline__ void store_pair4(__half* __restrict__ H,
                                            __half* __restrict__ L, size_t i,
                                            const float4& m4, const float4& xc,
                                            const float4& xp) {
    __half h0, l0, h1, l1, h2, l2, h3, l3;
    mix_store(m4.x, xc.x, xp.x, h0, l0);
    mix_store(m4.y, xc.y, xp.y, h1, l1);
    mix_store(m4.z, xc.z, xp.z, h2, l2);
    mix_store(m4.w, xc.w, xp.w, h3, l3);
    ((__half2*)(H + i))[0] = __halves2half2(h0, h1);
    ((__half2*)(H + i))[1] = __halves2half2(h2, h3);
    ((__half2*)(L + i))[0] = __halves2half2(l0, l1);
    ((__half2*)(L + i))[1] = __halves2half2(l2, l3);
}

__global__ void ln_mix3_kernel(const float* __restrict__ h,
                               const float* __restrict__ w, const float* __restrict__ b,
                               const float* __restrict__ mk, const float* __restrict__ mv,
                               const float* __restrict__ mr,
                               __half* __restrict__ xkh, __half* __restrict__ xkl,
                               __half* __restrict__ xvh, __half* __restrict__ xvl,
                               __half* __restrict__ xrh, __half* __restrict__ xrl) {
    size_t n = blockIdx.x;
    int t = (int)(n & (TSEQ - 1));
    float4 xc = ln_reg(h + n * HD, w, b);
    float4 xp = make_float4(0.f, 0.f, 0.f, 0.f);
    if (t) xp = ln_reg(h + (n - 1) * HD, w, b);
    size_t i = n * HD + (size_t)threadIdx.x * 4;
    store_pair4(xkh, xkl, i, ((const float4*)mk)[threadIdx.x], xc, xp);
    store_pair4(xvh, xvl, i, ((const float4*)mv)[threadIdx.x], xc, xp);
    store_pair4(xrh, xrl, i, ((const float4*)mr)[threadIdx.x], xc, xp);
}

__global__ void ln_mix2_kernel(const float* __restrict__ h,
                               const float* __restrict__ w, const float* __restrict__ b,
                               const float* __restrict__ mk, const float* __restrict__ mr,
                               __half* __restrict__ xkh, __half* __restrict__ xkl,
                               __half* __restrict__ xrh, __half* __restrict__ xrl) {
    size_t n = blockIdx.x;
    int t = (int)(n & (TSEQ - 1));
    float4 xc = ln_reg(h + n * HD, w, b);
    float4 xp = make_float4(0.f, 0.f, 0.f, 0.f);
    if (t) xp = ln_reg(h + (n - 1) * HD, w, b);
    size_t i = n * HD + (size_t)threadIdx.x * 4;
    store_pair4(xkh, xkl, i, ((const float4*)mk)[threadIdx.x], xc, xp);
    store_pair4(xrh, xrl, i, ((const float4*)mr)[threadIdx.x], xc, xp);
}

// ---------------- weight quantize fp32 -> fp16 (hi only) ----------------
__global__ void splitw_kernel(const float* __restrict__ src,
                              __half* __restrict__ h, int n4) {
    int i = (blockIdx.x * 256 + threadIdx.x);
    if (i >= n4) return;
    float4 v = ((const float4*)src)[i];
    __half2* Hp = (__half2*)(h + (size_t)i * 4);
    Hp[0] = __floats2half2_rn(v.x, v.y);
    Hp[1] = __floats2half2_rn(v.z, v.w);
}

// ---------------- WKV scan (emits y hi/lo fp16) ----------------
__global__ void wkv_kernel(const float* __restrict__ tf, const float* __restrict__ td,
                           const float* __restrict__ k, const float* __restrict__ v,
                           const float* __restrict__ r,
                           __half* __restrict__ yh, __half* __restrict__ yl) {
    int laneid = blockIdx.x * 256 + threadIdx.x;
    int b = laneid >> 10;
    int a = laneid & (AD - 1);
    float u = tf[a];
    float w = -__expf(td[a]);
    float aa = 0.f, bb = 0.f, pp = -1e38f;
    size_t base = ((size_t)b * TSEQ) * AD + a;
    float kt = k[base], vt = v[base], rt = r[base];
    for (int t = 0; t < TSEQ; t++) {
        size_t off = base + (size_t)t * AD;
        float kn = 0.f, vn = 0.f, rn = 0.f;
        if (t + 1 < TSEQ) { kn = k[off + AD]; vn = v[off + AD]; rn = r[off + AD]; }
        float uk = u + kt;
        float q = fmaxf(pp, uk);
        float e1 = __expf(uk - q);
        float e2 = __expf(pp - q);
        float num = fmaf(aa, e2, e1 * vt);
        float den = fmaf(bb, e2, e1);
        float o = rt * (num / den);
        __half hh, ll;
        split_h(o, hh, ll);
        yh[off] = hh; yl[off] = ll;
        float pw = pp + w;
        float q2 = fmaxf(pw, kt);
        float s1 = __expf(pw - q2);
        float s2 = __expf(kt - q2);
        aa = fmaf(s1, aa, s2 * vt);
        bb = fmaf(s1, bb, s2);
        pp = q2;
        kt = kn; vt = vn; rt = rn;
    }
}

// ---------------- orchestration ----------------
extern "C" void kernel_launch(void* const* d_in, const int* in_sizes, int n_in,
                              void* d_out, int out_size) {
    const int*   ids   = (const int*)d_in[0];
    const float* emb   = (const float*)d_in[1];
    const float* prew  = (const float*)d_in[2];
    const float* preb  = (const float*)d_in[3];
    const float* postw = (const float*)d_in[4];
    const float* postb = (const float*)d_in[5];
    const float* ln1w  = (const float*)d_in[6];
    const float* ln1b  = (const float*)d_in[7];
    const float* ln2w  = (const float*)d_in[8];
    const float* ln2b  = (const float*)d_in[9];
    const float* mxk   = (const float*)d_in[10];
    const float* mxv   = (const float*)d_in[11];
    const float* mxr   = (const float*)d_in[12];
    const float* wk    = (const float*)d_in[13];
    const float* wv    = (const float*)d_in[14];
    const float* wr    = (const float*)d_in[15];
    const float* wo    = (const float*)d_in[16];
    const float* tdec  = (const float*)d_in[17];
    const float* tfir  = (const float*)d_in[18];
    const float* fmk   = (const float*)d_in[19];
    const float* fmr   = (const float*)d_in[20];
    const float* fwk   = (const float*)d_in[21];
    const float* fwr   = (const float*)d_in[22];
    const float* fwv   = (const float*)d_in[23];
    float* out = (float*)d_out;

    void* p;
    cudaGetSymbolAddress(&p, g_h);    float* h  = (float*)p;
    cudaGetSymbolAddress(&p, g_k);    float* kb = (float*)p;
    cudaGetSymbolAddress(&p, g_v);    float* vb = (float*)p;
    cudaGetSymbolAddress(&p, g_r);    float* rb = (float*)p;
    cudaGetSymbolAddress(&p, g_xkh);  __half* xkh = (__half*)p;
    cudaGetSymbolAddress(&p, g_xkl);  __half* xkl = (__half*)p;
    cudaGetSymbolAddress(&p, g_xvh);  __half* xvh = (__half*)p;
    cudaGetSymbolAddress(&p, g_xvl);  __half* xvl = (__half*)p;
    cudaGetSymbolAddress(&p, g_xrh);  __half* xrh = (__half*)p;
    cudaGetSymbolAddress(&p, g_xrl);  __half* xrl = (__half*)p;
    cudaGetSymbolAddress(&p, g_yh);   __half* yh  = (__half*)p;
    cudaGetSymbolAddress(&p, g_yl);   __half* yl  = (__half*)p;
    cudaGetSymbolAddress(&p, g_fkh);  __half* fkh = (__half*)p;
    cudaGetSymbolAddress(&p, g_fkl);  __half* fkl = (__half*)p;
    cudaGetSymbolAddress(&p, g_wkh);  __half* wkh = (__half*)p;
    cudaGetSymbolAddress(&p, g_wvh);  __half* wvh = (__half*)p;
    cudaGetSymbolAddress(&p, g_wrh);  __half* wrh = (__half*)p;
    cudaGetSymbolAddress(&p, g_woh);  __half* woh = (__half*)p;
    cudaGetSymbolAddress(&p, g_fwkh); __half* fwkh = (__half*)p;
    cudaGetSymbolAddress(&p, g_fwrh); __half* fwrh = (__half*)p;
    cudaGetSymbolAddress(&p, g_fwvh); __half* fwvh = (__half*)p;

    cudaFuncSetAttribute(gemm_kvr, cudaFuncAttributeMaxDynamicSharedMemorySize, SMEM_SZ);
    cudaFuncSetAttribute(gemm_ffnpre, cudaFuncAttributeMaxDynamicSharedMemorySize, SMEM_SZ);
    cudaFuncSetAttribute(gemm_acc<3>, cudaFuncAttributeMaxDynamicSharedMemorySize, SMEM_SZ);
    cudaFuncSetAttribute(gemm_acc<4>, cudaFuncAttributeMaxDynamicSharedMemorySize, SMEM_SZ);

    // ---- weight quantize (once per launch; hi-only) ----
    const int nW  = NL * AD * HD;
    const int nWI = NL * FI * HD;
    splitw_kernel<<<nW / 1024, 256>>>(wk, wkh, nW / 4);
    splitw_kernel<<<nW / 1024, 256>>>(wv, wvh, nW / 4);
    splitw_kernel<<<nW / 1024, 256>>>(wr, wrh, nW / 4);
    splitw_kernel<<<nW / 1024, 256>>>(wo, woh, nW / 4);
    splitw_kernel<<<nWI / 1024, 256>>>(fwk, fwkh, nWI / 4);
    splitw_kernel<<<nW / 1024, 256>>>(fwr, fwrh, nW / 4);
    splitw_kernel<<<nWI / 1024, 256>>>(fwv, fwvh, nWI / 4);

    const dim3 gKVR(HD / BN, NTOK / BM, 3);          // (8, 64, 3)
    const dim3 gH(HD / BN, NTOK / BM);               // (8, 64)
    const dim3 gFFN(FI / BN + HD / BN, NTOK / BM);   // (40, 64)

    embed_ln_kernel<<<NTOK, 256>>>(ids, emb, prew, preb, h);

    for (int i = 0; i < NL; i++) {
        const size_t oW  = (size_t)i * AD * HD;
        const size_t oWI = (size_t)i * FI * HD;
        // ---- attention / time mix ----
        ln_mix3_kernel<<<NTOK, 256>>>(h, ln1w + i * HD, ln1b + i * HD,
                                      mxk + i * HD, mxv + i * HD, mxr + i * HD,
                                      xkh, xkl, xvh, xvl, xrh, xrl);
        gemm_kvr<<<gKVR, 256, SMEM_SZ>>>(xkh, xkl, xvh, xvl, xrh, xrl,
                                         wkh + oW, wvh + oW, wrh + oW,
                                         kb, vb, rb);
        wkv_kernel<<<NBB * AD / 256, 256>>>(tfir + i * AD, tdec + i * AD,
                                            kb, vb, rb, yh, yl);
        gemm_acc<3><<<gH, 256, SMEM_SZ>>>(yh, yl, woh + oW,
                                          h, nullptr, HD, AD);
        // ---- ffn / channel mix ----
        ln_mix2_kernel<<<NTOK, 256>>>(h, ln2w + i * HD, ln2b + i * HD,
                                      fmk + i * HD, fmr + i * HD,
                                      xkh, xkl, xrh, xrl);
        gemm_ffnpre<<<gFFN, 256, SMEM_SZ>>>(xkh, xkl, xrh, xrl,
                                            fwkh + oWI, fwrh + oW,
                                            fkh, fkl, rb);
        gemm_acc<4><<<gH, 256, SMEM_SZ>>>(fkh, fkl, fwvh + oWI,
                                          h, rb, HD, FI);
    }

    ln_kernel<<<NTOK, 256>>>(h, postw, postb, out);
}